// round 14
// baseline (speedup 1.0000x reference)
#include <cuda_runtime.h>
#include <cuda_bf16.h>
#include <math.h>
#include <stdint.h>

#define BSZ 4
#define SEQ 2048
#define EMB 1024
#define NH 16
#define HD 64
#define MTOT (BSZ*SEQ)   // 8192

// ---------------- scratch (__device__ globals; no allocs allowed) ----------
static __device__ __align__(256) __nv_bfloat16 g_xh[(size_t)MTOT*EMB];
static __device__ __align__(256) __nv_bfloat16 g_xl[(size_t)MTOT*EMB];
static __device__ __align__(256) __nv_bfloat16 g_wh[4][(size_t)EMB*EMB];
static __device__ __align__(256) __nv_bfloat16 g_wl[4][(size_t)EMB*EMB];
static __device__ __align__(256) __nv_bfloat16 g_Qh[(size_t)MTOT*EMB];
static __device__ __align__(256) __nv_bfloat16 g_Ql[(size_t)MTOT*EMB];
// compacted x rows (unmasked keys only) — K/V projection input
static __device__ __align__(256) __nv_bfloat16 g_cxh[(size_t)MTOT*EMB];
static __device__ __align__(256) __nv_bfloat16 g_cxl[(size_t)MTOT*EMB];
// mask-compacted K/V (written directly by the K/V projection GEMM; pad rows 0)
static __device__ __align__(256) __nv_bfloat16 g_cKh[(size_t)MTOT*EMB];
static __device__ __align__(256) __nv_bfloat16 g_cKl[(size_t)MTOT*EMB];
static __device__ __align__(256) __nv_bfloat16 g_cVh[(size_t)MTOT*EMB];
static __device__ __align__(256) __nv_bfloat16 g_cVl[(size_t)MTOT*EMB];
static __device__ int g_cnt[BSZ];
static __device__ int g_idx[BSZ*SEQ];
static __device__ int g_pos[BSZ*SEQ];   // src row -> compacted slot (or -1)

// ---------------- helpers --------------------------------------------------
__device__ __forceinline__ uint32_t smem_u32(const void* p) {
    uint32_t a;
    asm("{ .reg .u64 t; cvta.to.shared.u64 t, %1; cvt.u32.u64 %0, t; }"
        : "=r"(a) : "l"(p));
    return a;
}
__device__ __forceinline__ void cp16(uint32_t dst, const void* src) {
    asm volatile("cp.async.cg.shared.global [%0], [%1], 16;" :: "r"(dst), "l"(src));
}
#define CP_COMMIT() asm volatile("cp.async.commit_group;" ::: "memory")
#define CP_WAIT1()  asm volatile("cp.async.wait_group 1;" ::: "memory")
#define CP_WAIT0()  asm volatile("cp.async.wait_group 0;" ::: "memory")

__device__ __forceinline__ void ldsm4(uint32_t r[4], uint32_t a) {
    asm volatile("ldmatrix.sync.aligned.m8n8.x4.shared.b16 {%0,%1,%2,%3}, [%4];"
        : "=r"(r[0]), "=r"(r[1]), "=r"(r[2]), "=r"(r[3]) : "r"(a));
}
__device__ __forceinline__ void ldsm4t(uint32_t r[4], uint32_t a) {
    asm volatile("ldmatrix.sync.aligned.m8n8.x4.trans.shared.b16 {%0,%1,%2,%3}, [%4];"
        : "=r"(r[0]), "=r"(r[1]), "=r"(r[2]), "=r"(r[3]) : "r"(a));
}
__device__ __forceinline__ void mma16816(float c[4], const uint32_t a[4],
                                         uint32_t b0, uint32_t b1) {
    asm volatile("mma.sync.aligned.m16n8k16.row.col.f32.bf16.bf16.f32 "
        "{%0,%1,%2,%3}, {%4,%5,%6,%7}, {%8,%9}, {%0,%1,%2,%3};"
        : "+f"(c[0]), "+f"(c[1]), "+f"(c[2]), "+f"(c[3])
        : "r"(a[0]), "r"(a[1]), "r"(a[2]), "r"(a[3]), "r"(b0), "r"(b1));
}
__device__ __forceinline__ void split2(float v0, float v1, uint32_t& h, uint32_t& l) {
    __nv_bfloat162 hh = __floats2bfloat162_rn(v0, v1);
    float r0 = v0 - __bfloat162float(hh.x);
    float r1 = v1 - __bfloat162float(hh.y);
    __nv_bfloat162 ll = __floats2bfloat162_rn(r0, r1);
    h = *reinterpret_cast<uint32_t*>(&hh);
    l = *reinterpret_cast<uint32_t*>(&ll);
}
// [rows x 64] bf16 tile (128B rows), XOR swizzle: 8 chunks of 16B per row
#define SWZ(r, ch) (((r) << 7) | (((unsigned)((ch) ^ (r)) & 7u) << 4))
// [rows x 32] bf16 tile (64B rows): conflict-free for 8-row ldmatrix groups
#define SWZ32(r, ch) (((r) << 6) | (((unsigned)((ch) ^ (((r) >> 1) & 3)) & 3u) << 4))

// ---------------------------------------------------------------------------
// per-batch compaction: indices + inverse map + count. Runs BEFORE split.
// ---------------------------------------------------------------------------
__global__ __launch_bounds__(256)
void compact_kernel(const int* __restrict__ mask) {
    __shared__ int woff[8];
    const int b = blockIdx.x, t = threadIdx.x, lane = t & 31, w = t >> 5;
    const int* m = mask + b * SEQ;
    int v[8], cnt = 0;
#pragma unroll
    for (int i = 0; i < 8; i++) { v[i] = m[t * 8 + i]; cnt += (v[i] != 0); }
    int inc = cnt;
#pragma unroll
    for (int off = 1; off < 32; off <<= 1) {
        int nv = __shfl_up_sync(0xffffffffu, inc, off);
        if (lane >= off) inc += nv;
    }
    if (lane == 31) woff[w] = inc;
    __syncthreads();
    if (t == 0) {
        int run = 0;
#pragma unroll
        for (int j = 0; j < 8; j++) { int tmp = woff[j]; woff[j] = run; run += tmp; }
        g_cnt[b] = run;
    }
    __syncthreads();
    int off = woff[w] + inc - cnt;   // exclusive prefix for this thread
#pragma unroll
    for (int i = 0; i < 8; i++) {
        if (v[i]) { g_idx[b * SEQ + off] = t * 8 + i; g_pos[b * SEQ + t * 8 + i] = off; off++; }
        else        g_pos[b * SEQ + t * 8 + i] = -1;
    }
}

// ---------------------------------------------------------------------------
// fp32 -> bf16 hi/lo split; additionally scatters compacted rows for K/V proj
// ---------------------------------------------------------------------------
__global__ __launch_bounds__(256)
void split_kernel(const float* __restrict__ src,
                  __nv_bfloat16* __restrict__ hi, __nv_bfloat16* __restrict__ lo) {
    size_t i = (size_t)blockIdx.x * 256 + threadIdx.x;   // float4 index
    float4 v = ((const float4*)src)[i];
    uint32_t h0, l0, h1, l1;
    split2(v.x, v.y, h0, l0);
    split2(v.z, v.w, h1, l1);
    ((uint32_t*)hi)[2*i+0] = h0;  ((uint32_t*)hi)[2*i+1] = h1;
    ((uint32_t*)lo)[2*i+0] = l0;  ((uint32_t*)lo)[2*i+1] = l1;
    const int row = (int)(i >> 8);           // 256 float4 per 1024-wide row
    const int j = g_pos[row];
    if (j >= 0) {
        const int b = row >> 11;
        const size_t d = (((size_t)(b * SEQ) + j) << 10) + ((i & 255) << 2);
        *(uint32_t*)(g_cxh + d)     = h0;  *(uint32_t*)(g_cxh + d + 2) = h1;
        *(uint32_t*)(g_cxl + d)     = l0;  *(uint32_t*)(g_cxl + d + 2) = l1;
    }
}

__global__ __launch_bounds__(256)
void tsplit4_kernel(const float* __restrict__ W0, const float* __restrict__ W1,
                    const float* __restrict__ W2, const float* __restrict__ W3,
                    __nv_bfloat16* __restrict__ ThB, __nv_bfloat16* __restrict__ TlB) {
    __shared__ float sm[32][33];
    const int tx = threadIdx.x, ty = threadIdx.y;
    const int n0 = blockIdx.x * 32, k0 = blockIdx.y * 32;
    const int z = blockIdx.z;
    const float* W = (z == 0) ? W0 : (z == 1 ? W1 : (z == 2 ? W2 : W3));
    __nv_bfloat16* Th = ThB + (size_t)z * EMB * EMB;
    __nv_bfloat16* Tl = TlB + (size_t)z * EMB * EMB;
#pragma unroll
    for (int r = ty; r < 32; r += 8)
        sm[r][tx] = W[(size_t)(k0 + r) * EMB + n0 + tx];
    __syncthreads();
#pragma unroll
    for (int r = ty; r < 32; r += 8) {
        float v = sm[tx][r];
        __nv_bfloat16 h = __float2bfloat16_rn(v);
        __nv_bfloat16 l = __float2bfloat16_rn(v - __bfloat162float(h));
        Th[(size_t)(n0 + r) * EMB + k0 + tx] = h;
        Tl[(size_t)(n0 + r) * EMB + k0 + tx] = l;
    }
}

// ---------------------------------------------------------------------------
// bf16x3 warp-MMA GEMM (R11 WIN, unchanged). K-chunk 32, 3 stages, occ 2.
// HEADOUT=1: z=0 Q (all rows); z=1,2 K,V over compacted rows (early exit).
// ---------------------------------------------------------------------------
template<int HEADOUT>
__global__ __launch_bounds__(256, 2)
void gemm_mma(const __nv_bfloat16* __restrict__ Ah, const __nv_bfloat16* __restrict__ Al,
              const __nv_bfloat16* __restrict__ WhBase, const __nv_bfloat16* __restrict__ WlBase,
              const float* __restrict__ b0p, const float* __restrict__ b1p,
              const float* __restrict__ b2p, float* __restrict__ Co,
              __nv_bfloat16* __restrict__ C0h, __nv_bfloat16* __restrict__ C0l,
              __nv_bfloat16* __restrict__ C1h, __nv_bfloat16* __restrict__ C1l,
              __nv_bfloat16* __restrict__ C2h, __nv_bfloat16* __restrict__ C2l) {
    extern __shared__ __align__(128) char smem[];
    const uint32_t sb = smem_u32(smem);
    const int t = threadIdx.x, lane = t & 31, w = t >> 5;
    const int wm = (w & 3) * 32, wn = (w >> 2) * 64;
    const int my = blockIdx.y, n0 = blockIdx.x << 7;
    const int z = HEADOUT ? blockIdx.z : 0;

    const __nv_bfloat16 *Aph, *Apl;
    int bsel = 0, tile = 0;
    if (HEADOUT && z > 0) {
        bsel = my >> 4; tile = my & 15;
        if ((tile << 7) >= g_cnt[bsel]) return;
        const size_t ao = ((size_t)(bsel * SEQ) + ((size_t)tile << 7)) * EMB;
        Aph = g_cxh + ao;  Apl = g_cxl + ao;
    } else {
        const size_t ao = ((size_t)my << 7) * EMB;
        Aph = Ah + ao;  Apl = Al + ao;
    }

    const __nv_bfloat16* Bh = WhBase + (size_t)z * EMB * EMB;
    const __nv_bfloat16* Bl = WlBase + (size_t)z * EMB * EMB;
    const float* bias = (z == 0) ? b0p : (z == 1 ? b1p : b2p);
    __nv_bfloat16* Ch = (z == 0) ? C0h : (z == 1 ? C1h : C2h);
    __nv_bfloat16* Cl = (z == 0) ? C0l : (z == 1 ? C1l : C2l);

    auto issue = [&](int kb, int st) {
        const uint32_t s0 = sb + st * 32768;
        const int kc = kb << 5;
#pragma unroll
        for (int i = 0; i < 2; i++) {
            int idx = t + (i << 8);
            int row = idx >> 2, ch = idx & 3;
            int so = SWZ32(row, ch);
            size_t ga = (size_t)row * EMB + kc + (ch << 3);
            size_t gb = (size_t)(n0 + row) * EMB + kc + (ch << 3);
            cp16(s0 +         so, Aph + ga);
            cp16(s0 +  8192 + so, Apl + ga);
            cp16(s0 + 16384 + so, Bh + gb);
            cp16(s0 + 24576 + so, Bl + gb);
        }
    };

    float c[2][8][4];
#pragma unroll
    for (int i = 0; i < 2; i++)
#pragma unroll
        for (int j = 0; j < 8; j++)
#pragma unroll
            for (int k = 0; k < 4; k++) c[i][j][k] = 0.f;

    issue(0, 0); CP_COMMIT();
    issue(1, 1); CP_COMMIT();

    for (int kb = 0; kb < 32; kb++) {
        CP_WAIT1();
        __syncthreads();
        if (kb + 2 < 32) issue(kb + 2, (kb + 2) % 3);
        CP_COMMIT();

        const uint32_t s0 = sb + (kb % 3) * 32768;
        const uint32_t sAh = s0, sAl = s0 + 8192, sBh = s0 + 16384, sBl = s0 + 24576;
#pragma unroll
        for (int s = 0; s < 2; s++) {
            const int ch = 2 * s + (lane >> 4);
            uint32_t ah[2][4], al[2][4];
#pragma unroll
            for (int mt = 0; mt < 2; mt++) {
                int r = wm + mt * 16 + (lane & 15);
                ldsm4(ah[mt], sAh + SWZ32(r, ch));
                ldsm4(al[mt], sAl + SWZ32(r, ch));
            }
#pragma unroll
            for (int g = 0; g < 4; g++) {
                int r = wn + g * 16 + (lane & 15);
                uint32_t bh[4], bl[4];
                ldsm4(bh, sBh + SWZ32(r, ch));
                ldsm4(bl, sBl + SWZ32(r, ch));
#pragma unroll
                for (int mt = 0; mt < 2; mt++) {
                    mma16816(c[mt][2*g],   ah[mt], bh[0], bh[2]);
                    mma16816(c[mt][2*g+1], ah[mt], bh[1], bh[3]);
                    mma16816(c[mt][2*g],   ah[mt], bl[0], bl[2]);
                    mma16816(c[mt][2*g+1], ah[mt], bl[1], bl[3]);
                    mma16816(c[mt][2*g],   al[mt], bh[0], bh[2]);
                    mma16816(c[mt][2*g+1], al[mt], bh[1], bh[3]);
                }
            }
        }
    }

#pragma unroll
    for (int mt = 0; mt < 2; mt++) {
#pragma unroll
        for (int nt = 0; nt < 8; nt++) {
            const int col = n0 + wn + nt * 8 + ((lane & 3) << 1);
            const float b0 = bias[col], b1 = bias[col + 1];
            const int r0 = wm + mt * 16 + (lane >> 2);
#pragma unroll
            for (int half = 0; half < 2; half++) {
                const int r = r0 + half * 8;
                const float v0 = c[mt][nt][half*2+0] + b0;
                const float v1 = c[mt][nt][half*2+1] + b1;
                if (HEADOUT) {
                    uint32_t h2, l2;
                    split2(v0, v1, h2, l2);
                    const int hd = col >> 6, d0 = col & 63;
                    size_t off;
                    if (z == 0) {
                        const int m = (my << 7) + r;
                        const int bb = m >> 11, srow = m & 2047;
                        off = (((size_t)(bb * NH + hd)) * SEQ + srow) * HD + d0;
                    } else {
                        const int j = (tile << 7) + r;
                        off = (((size_t)(bsel * NH + hd)) * SEQ + j) * HD + d0;
                    }
                    *(uint32_t*)(Ch + off) = h2;
                    *(uint32_t*)(Cl + off) = l2;
                } else {
                    const int m = (my << 7) + r;
                    *(float2*)(Co + (size_t)m * EMB + col) = make_float2(v0, v1);
                }
            }
        }
    }
}

// ---------------------------------------------------------------------------
// Flash attention, split-K within CTA: 8 warps = 4 q-groups (m32) x 2 k-halves
// (k32). Independent online softmax per warp; single merge at the end.
// R14 de-risk: merge scratch lives in the DEAD Q region (no cp.async ever
// targets Q after the prologue) + explicit make_float4 stores (no array cast).
// smem: Q 32KB (reused as merge ob) | KV st0 32KB (first 4KB reused as mlb)
//       | KV st1 32KB = 96KB, occ 2.
// ---------------------------------------------------------------------------
__global__ __launch_bounds__(256, 2)
void attn_mma() {
    extern __shared__ __align__(128) char smem[];
    const uint32_t sQh = smem_u32(smem);
    const uint32_t sQl = sQh + 16384;
    const uint32_t sKV = sQh + 32768;

    const int t = threadIdx.x, lane = t & 31, w = t >> 5;
    const int wq = w & 3, kh = w >> 2;
    const int qb = blockIdx.x, h = blockIdx.y, b = blockIdx.z;
    const size_t base = ((size_t)(b * NH + h)) * SEQ * HD;
    const int n = g_cnt[b];
    const int ntiles = (n + 63) >> 6;

    auto issue_kv = [&](int kb, int st) {
        const uint32_t s0 = sKV + st * 32768;
#pragma unroll
        for (int i = 0; i < 2; i++) {
            int idx = t + (i << 8);
            int row = idx >> 3, ch = idx & 7;
            int so = SWZ(row, ch);
            size_t ga = base + (size_t)(kb * 64 + row) * HD + (ch << 3);
            cp16(s0 +         so, g_cKh + ga);
            cp16(s0 +  8192 + so, g_cKl + ga);
            cp16(s0 + 16384 + so, g_cVh + ga);
            cp16(s0 + 24576 + so, g_cVl + ga);
        }
    };

#pragma unroll
    for (int i = 0; i < 4; i++) {
        int idx = t + (i << 8);
        int row = idx >> 3, ch = idx & 7;
        int so = SWZ(row, ch);
        size_t ga = base + (size_t)(qb * 128 + row) * HD + (ch << 3);
        cp16(sQh + so, g_Qh + ga);
        cp16(sQl + so, g_Ql + ga);
    }
    issue_kv(0, 0); CP_COMMIT();

    float o[2][8][4];
#pragma unroll
    for (int mt = 0; mt < 2; mt++)
#pragma unroll
        for (int i = 0; i < 8; i++)
#pragma unroll
            for (int j = 0; j < 4; j++) o[mt][i][j] = 0.f;
    float mrow[2][2] = {{-INFINITY, -INFINITY}, {-INFINITY, -INFINITY}};
    float lsum[2][2] = {{0.f, 0.f}, {0.f, 0.f}};

    for (int kb = 0; kb < ntiles; kb++) {
        CP_WAIT0();
        __syncthreads();
        if (kb + 1 < ntiles) issue_kv(kb + 1, (kb + 1) & 1);
        CP_COMMIT();

        const uint32_t s0 = sKV + (kb & 1) * 32768;
        const uint32_t sKh = s0, sKl = s0 + 8192, sVh = s0 + 16384, sVl = s0 + 24576;

        // ---- S = Q K^T over this warp's k-half (m32 x n32, bf16x3) ----
        float c[2][4][4];
#pragma unroll
        for (int mt = 0; mt < 2; mt++)
#pragma unroll
            for (int i = 0; i < 4; i++)
#pragma unroll
                for (int j = 0; j < 4; j++) c[mt][i][j] = 0.f;
#pragma unroll
        for (int s = 0; s < 4; s++) {
            const int ch = 2 * s + (lane >> 4);
            uint32_t ah[2][4], al[2][4];
#pragma unroll
            for (int mt = 0; mt < 2; mt++) {
                const int rq = wq * 32 + mt * 16 + (lane & 15);
                ldsm4(ah[mt], sQh + SWZ(rq, ch));
                ldsm4(al[mt], sQl + SWZ(rq, ch));
            }
#pragma unroll
            for (int g = 0; g < 2; g++) {
                const int rk = kh * 32 + g * 16 + (lane & 15);
                uint32_t bh[4], bl[4];
                ldsm4(bh, sKh + SWZ(rk, ch));
                ldsm4(bl, sKl + SWZ(rk, ch));
#pragma unroll
                for (int mt = 0; mt < 2; mt++) {
                    mma16816(c[mt][2*g],   ah[mt], bh[0], bh[2]);
                    mma16816(c[mt][2*g+1], ah[mt], bh[1], bh[3]);
                    mma16816(c[mt][2*g],   ah[mt], bl[0], bl[2]);
                    mma16816(c[mt][2*g+1], ah[mt], bl[1], bl[3]);
                    mma16816(c[mt][2*g],   al[mt], bh[0], bh[2]);
                    mma16816(c[mt][2*g+1], al[mt], bh[1], bh[3]);
                }
            }
        }

        // ---- scale + validity; online softmax per mt ----
        const int cb = (lane & 3) << 1;
#pragma unroll
        for (int mt = 0; mt < 2; mt++) {
#pragma unroll
            for (int nt = 0; nt < 4; nt++) {
                const int col = kb * 64 + kh * 32 + nt * 8 + cb;
                const bool v0 = col < n, v1 = col + 1 < n;
                c[mt][nt][0] = v0 ? c[mt][nt][0] * 0.125f : -1.0e9f;
                c[mt][nt][1] = v1 ? c[mt][nt][1] * 0.125f : -1.0e9f;
                c[mt][nt][2] = v0 ? c[mt][nt][2] * 0.125f : -1.0e9f;
                c[mt][nt][3] = v1 ? c[mt][nt][3] * 0.125f : -1.0e9f;
            }
            float mxA = -INFINITY, mxB = -INFINITY;
#pragma unroll
            for (int nt = 0; nt < 4; nt++) {
                mxA = fmaxf(mxA, fmaxf(c[mt][nt][0], c[mt][nt][1]));
                mxB = fmaxf(mxB, fmaxf(c[mt][nt][2], c[mt][nt][3]));
            }
#pragma unroll
            for (int off = 1; off < 4; off <<= 1) {
                mxA = fmaxf(mxA, __shfl_xor_sync(0xffffffffu, mxA, off));
                mxB = fmaxf(mxB, __shfl_xor_sync(0xffffffffu, mxB, off));
            }
            const float nmA = fmaxf(mrow[mt][0], mxA), nmB = fmaxf(mrow[mt][1], mxB);
            const float scA = __expf(mrow[mt][0] - nmA), scB = __expf(mrow[mt][1] - nmB);
            mrow[mt][0] = nmA; mrow[mt][1] = nmB;
            float sA = 0.f, sB = 0.f;
#pragma unroll
            for (int nt = 0; nt < 4; nt++) {
                c[mt][nt][0] = __expf(c[mt][nt][0] - nmA);
                c[mt][nt][1] = __expf(c[mt][nt][1] - nmA);
                c[mt][nt][2] = __expf(c[mt][nt][2] - nmB);
                c[mt][nt][3] = __expf(c[mt][nt][3] - nmB);
                sA += c[mt][nt][0] + c[mt][nt][1];
                sB += c[mt][nt][2] + c[mt][nt][3];
            }
#pragma unroll
            for (int off = 1; off < 4; off <<= 1) {
                sA += __shfl_xor_sync(0xffffffffu, sA, off);
                sB += __shfl_xor_sync(0xffffffffu, sB, off);
            }
            lsum[mt][0] = lsum[mt][0] * scA + sA;
            lsum[mt][1] = lsum[mt][1] * scB + sB;
#pragma unroll
            for (int nt = 0; nt < 8; nt++) {
                o[mt][nt][0] *= scA; o[mt][nt][1] *= scA;
                o[mt][nt][2] *= scB; o[mt][nt][3] *= scB;
            }
        }

        // ---- O += P V over this warp's k-half (V shared across mt) ----
#pragma unroll
        for (int kt = 0; kt < 2; kt++) {
            uint32_t ph[2][4], pl[2][4];
#pragma unroll
            for (int mt = 0; mt < 2; mt++) {
                split2(c[mt][2*kt][0],   c[mt][2*kt][1],   ph[mt][0], pl[mt][0]);
                split2(c[mt][2*kt][2],   c[mt][2*kt][3],   ph[mt][1], pl[mt][1]);
                split2(c[mt][2*kt+1][0], c[mt][2*kt+1][1], ph[mt][2], pl[mt][2]);
                split2(c[mt][2*kt+1][2], c[mt][2*kt+1][3], ph[mt][3], pl[mt][3]);
            }
            const int rv = kh * 32 + kt * 16 + (lane & 15);
#pragma unroll
            for (int g = 0; g < 4; g++) {
                const int chv = 2 * g + (lane >> 4);
                uint32_t vh[4], vl[4];
                ldsm4t(vh, sVh + SWZ(rv, chv));
                ldsm4t(vl, sVl + SWZ(rv, chv));
#pragma unroll
                for (int mt = 0; mt < 2; mt++) {
                    mma16816(o[mt][2*g],   ph[mt], vh[0], vh[1]);
                    mma16816(o[mt][2*g+1], ph[mt], vh[2], vh[3]);
                    mma16816(o[mt][2*g],   ph[mt], vl[0], vl[1]);
                    mma16816(o[mt][2*g+1], ph[mt], vl[2], vl[3]);
                    mma16816(o[mt][2*g],   pl[mt], vh[0], vh[1]);
                    mma16816(o[mt][2*g+1], pl[mt], vh[2], vh[3]);
                }
            }
        }
    }

    // ---- split-K merge (scratch = dead Q region + head of KV stage 0) ----
    __syncthreads();   // all Q/KV smem reads done; regions reusable
    if (kh == 1) {
        char* ob = smem + wq * 8192;                      // Q region
        float* mlb = (float*)(smem + 32768 + wq * 1024) + lane * 8;
#pragma unroll
        for (int mt = 0; mt < 2; mt++)
#pragma unroll
            for (int nt = 0; nt < 8; nt++)
                *(float4*)(ob + (mt * 8 + nt) * 512 + lane * 16) =
                    make_float4(o[mt][nt][0], o[mt][nt][1], o[mt][nt][2], o[mt][nt][3]);
        mlb[0] = mrow[0][0]; mlb[1] = mrow[0][1];
        mlb[2] = mrow[1][0]; mlb[3] = mrow[1][1];
        mlb[4] = lsum[0][0]; mlb[5] = lsum[0][1];
        mlb[6] = lsum[1][0]; mlb[7] = lsum[1][1];
    }
    __syncthreads();
    if (kh == 0) {
        const char* ob = smem + wq * 8192;
        const float* mlb = (const float*)(smem + 32768 + wq * 1024) + lane * 8;
        float fA[2][2], fB[2][2], inv[2][2];
#pragma unroll
        for (int mt = 0; mt < 2; mt++)
#pragma unroll
            for (int hf = 0; hf < 2; hf++) {
                const float mB = mlb[mt * 2 + hf], lB = mlb[4 + mt * 2 + hf];
                const float mm = fmaxf(mrow[mt][hf], mB);
                const float a = __expf(mrow[mt][hf] - mm);
                const float p = __expf(mB - mm);
                fA[mt][hf] = a; fB[mt][hf] = p;
                inv[mt][hf] = 1.f / (lsum[mt][hf] * a + lB * p);
            }
        const int colb = (lane & 3) << 1;
#pragma unroll
        for (int mt = 0; mt < 2; mt++) {
            const int rA = qb * 128 + wq * 32 + mt * 16 + (lane >> 2);
#pragma unroll
            for (int nt = 0; nt < 8; nt++) {
                const float4 pb = *(const float4*)(ob + (mt * 8 + nt) * 512 + lane * 16);
                const float v0 = (o[mt][nt][0] * fA[mt][0] + pb.x * fB[mt][0]) * inv[mt][0];
                const float v1 = (o[mt][nt][1] * fA[mt][0] + pb.y * fB[mt][0]) * inv[mt][0];
                const float v2 = (o[mt][nt][2] * fA[mt][1] + pb.z * fB[mt][1]) * inv[mt][1];
                const float v3 = (o[mt][nt][3] * fA[mt][1] + pb.w * fB[mt][1]) * inv[mt][1];
                const int col = h * HD + nt * 8 + colb;
                uint32_t h2, l2;
                split2(v0, v1, h2, l2);
                size_t off = ((size_t)b * SEQ + rA) * EMB + col;
                *(uint32_t*)(g_xh + off) = h2;
                *(uint32_t*)(g_xl + off) = l2;
                split2(v2, v3, h2, l2);
                off = ((size_t)b * SEQ + rA + 8) * EMB + col;
                *(uint32_t*)(g_xh + off) = h2;
                *(uint32_t*)(g_xl + off) = l2;
            }
        }
    }
}

// ---------------------------------------------------------------------------
extern "C" void kernel_launch(void* const* d_in, const int* in_sizes, int n_in,
                              void* d_out, int out_size) {
    const float* x  = (const float*)d_in[0];
    const int*  mask = (const int*)d_in[1];
    const float* Wq = (const float*)d_in[2];
    const float* bq = (const float*)d_in[3];
    const float* Wk = (const float*)d_in[4];
    const float* bk = (const float*)d_in[5];
    const float* Wv = (const float*)d_in[6];
    const float* bv = (const float*)d_in[7];
    const float* Wo = (const float*)d_in[8];
    const float* bo = (const float*)d_in[9];

    __nv_bfloat16 *xh, *xl, *wh, *wl, *Qh, *Ql, *cKh, *cKl, *cVh, *cVl;
    cudaGetSymbolAddress((void**)&xh, g_xh);
    cudaGetSymbolAddress((void**)&xl, g_xl);
    cudaGetSymbolAddress((void**)&wh, g_wh);
    cudaGetSymbolAddress((void**)&wl, g_wl);
    cudaGetSymbolAddress((void**)&Qh, g_Qh);
    cudaGetSymbolAddress((void**)&Ql, g_Ql);
    cudaGetSymbolAddress((void**)&cKh, g_cKh);
    cudaGetSymbolAddress((void**)&cKl, g_cKl);
    cudaGetSymbolAddress((void**)&cVh, g_cVh);
    cudaGetSymbolAddress((void**)&cVl, g_cVl);
    const size_t WS = (size_t)EMB * EMB;

    const int GEMM_SMEM = 3 * 32768;           // 96KB -> occ 2
    const int ATTN_SMEM = 98304;               // 96KB -> occ 2
    cudaFuncSetAttribute(gemm_mma<1>, cudaFuncAttributeMaxDynamicSharedMemorySize, GEMM_SMEM);
    cudaFuncSetAttribute(gemm_mma<0>, cudaFuncAttributeMaxDynamicSharedMemorySize, GEMM_SMEM);
    cudaFuncSetAttribute(attn_mma,    cudaFuncAttributeMaxDynamicSharedMemorySize, ATTN_SMEM);

    // compaction first (mask only), then split (also scatters compacted rows)
    compact_kernel<<<BSZ, 256>>>(mask);
    split_kernel<<<(MTOT*EMB)/4/256, 256>>>(x, xh, xl);
    tsplit4_kernel<<<dim3(32,32,4), dim3(32,8)>>>(Wq, Wk, Wv, Wo, wh, wl);

    // fused QKV projection: z=0 Q (all rows), z=1 K / z=2 V (compacted rows)
    gemm_mma<1><<<dim3(EMB/128, MTOT/128, 3), 256, GEMM_SMEM>>>(
        xh, xl, wh, wl, bq, bk, bv, nullptr, Qh, Ql, cKh, cKl, cVh, cVl);

    // split-K attention over compacted keys -> bf16 hi/lo into xh/xl
    attn_mma<<<dim3(SEQ/128, NH, BSZ), 256, ATTN_SMEM>>>();

    // O projection -> fp32 d_out
    gemm_mma<0><<<dim3(EMB/128, MTOT/128, 1), 256, GEMM_SMEM>>>(
        xh, xl, wh + 3*WS, wl + 3*WS, bo, bo, bo, (float*)d_out,
        nullptr, nullptr, nullptr, nullptr, nullptr, nullptr);
}

// round 15
// speedup vs baseline: 1.0465x; 1.0465x over previous
#include <cuda_runtime.h>
#include <cuda_bf16.h>
#include <math.h>
#include <stdint.h>

#define BSZ 4
#define SEQ 2048
#define EMB 1024
#define NH 16
#define HD 64
#define MTOT (BSZ*SEQ)   // 8192

// ---------------- scratch (__device__ globals; no allocs allowed) ----------
static __device__ __align__(256) __nv_bfloat16 g_xh[(size_t)MTOT*EMB];
static __device__ __align__(256) __nv_bfloat16 g_xl[(size_t)MTOT*EMB];
static __device__ __align__(256) __nv_bfloat16 g_wh[4][(size_t)EMB*EMB];
static __device__ __align__(256) __nv_bfloat16 g_wl[4][(size_t)EMB*EMB];
static __device__ __align__(256) __nv_bfloat16 g_Qh[(size_t)MTOT*EMB];
static __device__ __align__(256) __nv_bfloat16 g_Ql[(size_t)MTOT*EMB];
// compacted x rows (unmasked keys only) — K/V projection input
static __device__ __align__(256) __nv_bfloat16 g_cxh[(size_t)MTOT*EMB];
static __device__ __align__(256) __nv_bfloat16 g_cxl[(size_t)MTOT*EMB];
// mask-compacted K/V (written directly by the K/V projection GEMM; pad rows 0)
static __device__ __align__(256) __nv_bfloat16 g_cKh[(size_t)MTOT*EMB];
static __device__ __align__(256) __nv_bfloat16 g_cKl[(size_t)MTOT*EMB];
static __device__ __align__(256) __nv_bfloat16 g_cVh[(size_t)MTOT*EMB];
static __device__ __align__(256) __nv_bfloat16 g_cVl[(size_t)MTOT*EMB];
static __device__ int g_cnt[BSZ];
static __device__ int g_idx[BSZ*SEQ];
static __device__ int g_pos[BSZ*SEQ];   // src row -> compacted slot (or -1)

// ---------------- helpers --------------------------------------------------
__device__ __forceinline__ uint32_t smem_u32(const void* p) {
    uint32_t a;
    asm("{ .reg .u64 t; cvta.to.shared.u64 t, %1; cvt.u32.u64 %0, t; }"
        : "=r"(a) : "l"(p));
    return a;
}
__device__ __forceinline__ void cp16(uint32_t dst, const void* src) {
    asm volatile("cp.async.cg.shared.global [%0], [%1], 16;" :: "r"(dst), "l"(src));
}
#define CP_COMMIT() asm volatile("cp.async.commit_group;" ::: "memory")
#define CP_WAIT1()  asm volatile("cp.async.wait_group 1;" ::: "memory")
#define CP_WAIT0()  asm volatile("cp.async.wait_group 0;" ::: "memory")

__device__ __forceinline__ void ldsm4(uint32_t r[4], uint32_t a) {
    asm volatile("ldmatrix.sync.aligned.m8n8.x4.shared.b16 {%0,%1,%2,%3}, [%4];"
        : "=r"(r[0]), "=r"(r[1]), "=r"(r[2]), "=r"(r[3]) : "r"(a));
}
__device__ __forceinline__ void ldsm4t(uint32_t r[4], uint32_t a) {
    asm volatile("ldmatrix.sync.aligned.m8n8.x4.trans.shared.b16 {%0,%1,%2,%3}, [%4];"
        : "=r"(r[0]), "=r"(r[1]), "=r"(r[2]), "=r"(r[3]) : "r"(a));
}
__device__ __forceinline__ void mma16816(float c[4], const uint32_t a[4],
                                         uint32_t b0, uint32_t b1) {
    asm volatile("mma.sync.aligned.m16n8k16.row.col.f32.bf16.bf16.f32 "
        "{%0,%1,%2,%3}, {%4,%5,%6,%7}, {%8,%9}, {%0,%1,%2,%3};"
        : "+f"(c[0]), "+f"(c[1]), "+f"(c[2]), "+f"(c[3])
        : "r"(a[0]), "r"(a[1]), "r"(a[2]), "r"(a[3]), "r"(b0), "r"(b1));
}
__device__ __forceinline__ void split2(float v0, float v1, uint32_t& h, uint32_t& l) {
    __nv_bfloat162 hh = __floats2bfloat162_rn(v0, v1);
    float r0 = v0 - __bfloat162float(hh.x);
    float r1 = v1 - __bfloat162float(hh.y);
    __nv_bfloat162 ll = __floats2bfloat162_rn(r0, r1);
    h = *reinterpret_cast<uint32_t*>(&hh);
    l = *reinterpret_cast<uint32_t*>(&ll);
}
// [rows x 64] bf16 tile (128B rows), XOR swizzle: 8 chunks of 16B per row
#define SWZ(r, ch) (((r) << 7) | (((unsigned)((ch) ^ (r)) & 7u) << 4))
// [rows x 32] bf16 tile (64B rows): conflict-free for 8-row ldmatrix groups
#define SWZ32(r, ch) (((r) << 6) | (((unsigned)((ch) ^ (((r) >> 1) & 3)) & 3u) << 4))

// ---------------------------------------------------------------------------
// per-batch compaction: indices + inverse map + count. Runs BEFORE split.
// ---------------------------------------------------------------------------
__global__ __launch_bounds__(256)
void compact_kernel(const int* __restrict__ mask) {
    __shared__ int woff[8];
    const int b = blockIdx.x, t = threadIdx.x, lane = t & 31, w = t >> 5;
    const int* m = mask + b * SEQ;
    int v[8], cnt = 0;
#pragma unroll
    for (int i = 0; i < 8; i++) { v[i] = m[t * 8 + i]; cnt += (v[i] != 0); }
    int inc = cnt;
#pragma unroll
    for (int off = 1; off < 32; off <<= 1) {
        int nv = __shfl_up_sync(0xffffffffu, inc, off);
        if (lane >= off) inc += nv;
    }
    if (lane == 31) woff[w] = inc;
    __syncthreads();
    if (t == 0) {
        int run = 0;
#pragma unroll
        for (int j = 0; j < 8; j++) { int tmp = woff[j]; woff[j] = run; run += tmp; }
        g_cnt[b] = run;
    }
    __syncthreads();
    int off = woff[w] + inc - cnt;   // exclusive prefix for this thread
#pragma unroll
    for (int i = 0; i < 8; i++) {
        if (v[i]) { g_idx[b * SEQ + off] = t * 8 + i; g_pos[b * SEQ + t * 8 + i] = off; off++; }
        else        g_pos[b * SEQ + t * 8 + i] = -1;
    }
}

// ---------------------------------------------------------------------------
// fp32 -> bf16 hi/lo split; additionally scatters compacted rows for K/V proj
// ---------------------------------------------------------------------------
__global__ __launch_bounds__(256)
void split_kernel(const float* __restrict__ src,
                  __nv_bfloat16* __restrict__ hi, __nv_bfloat16* __restrict__ lo) {
    size_t i = (size_t)blockIdx.x * 256 + threadIdx.x;   // float4 index
    float4 v = ((const float4*)src)[i];
    uint32_t h0, l0, h1, l1;
    split2(v.x, v.y, h0, l0);
    split2(v.z, v.w, h1, l1);
    ((uint32_t*)hi)[2*i+0] = h0;  ((uint32_t*)hi)[2*i+1] = h1;
    ((uint32_t*)lo)[2*i+0] = l0;  ((uint32_t*)lo)[2*i+1] = l1;
    const int row = (int)(i >> 8);           // 256 float4 per 1024-wide row
    const int j = g_pos[row];
    if (j >= 0) {
        const int b = row >> 11;
        const size_t d = (((size_t)(b * SEQ) + j) << 10) + ((i & 255) << 2);
        *(uint32_t*)(g_cxh + d)     = h0;  *(uint32_t*)(g_cxh + d + 2) = h1;
        *(uint32_t*)(g_cxl + d)     = l0;  *(uint32_t*)(g_cxl + d + 2) = l1;
    }
}

__global__ __launch_bounds__(256)
void tsplit4_kernel(const float* __restrict__ W0, const float* __restrict__ W1,
                    const float* __restrict__ W2, const float* __restrict__ W3,
                    __nv_bfloat16* __restrict__ ThB, __nv_bfloat16* __restrict__ TlB) {
    __shared__ float sm[32][33];
    const int tx = threadIdx.x, ty = threadIdx.y;
    const int n0 = blockIdx.x * 32, k0 = blockIdx.y * 32;
    const int z = blockIdx.z;
    const float* W = (z == 0) ? W0 : (z == 1 ? W1 : (z == 2 ? W2 : W3));
    __nv_bfloat16* Th = ThB + (size_t)z * EMB * EMB;
    __nv_bfloat16* Tl = TlB + (size_t)z * EMB * EMB;
#pragma unroll
    for (int r = ty; r < 32; r += 8)
        sm[r][tx] = W[(size_t)(k0 + r) * EMB + n0 + tx];
    __syncthreads();
#pragma unroll
    for (int r = ty; r < 32; r += 8) {
        float v = sm[tx][r];
        __nv_bfloat16 h = __float2bfloat16_rn(v);
        __nv_bfloat16 l = __float2bfloat16_rn(v - __bfloat162float(h));
        Th[(size_t)(n0 + r) * EMB + k0 + tx] = h;
        Tl[(size_t)(n0 + r) * EMB + k0 + tx] = l;
    }
}

// ---------------------------------------------------------------------------
// bf16x3 warp-MMA GEMM. K-chunk 32, 3 stages, occ 2.
// R15: term-major mma issue over g-pairs -> same-accumulator reuse distance
// 2 -> 8 (mma latency covered); per-accumulator addition order unchanged
// (hh, hl, lh) so results are bit-identical to R11.
// HEADOUT=1: z=0 Q (all rows); z=1,2 K,V over compacted rows (early exit).
// ---------------------------------------------------------------------------
template<int HEADOUT>
__global__ __launch_bounds__(256, 2)
void gemm_mma(const __nv_bfloat16* __restrict__ Ah, const __nv_bfloat16* __restrict__ Al,
              const __nv_bfloat16* __restrict__ WhBase, const __nv_bfloat16* __restrict__ WlBase,
              const float* __restrict__ b0p, const float* __restrict__ b1p,
              const float* __restrict__ b2p, float* __restrict__ Co,
              __nv_bfloat16* __restrict__ C0h, __nv_bfloat16* __restrict__ C0l,
              __nv_bfloat16* __restrict__ C1h, __nv_bfloat16* __restrict__ C1l,
              __nv_bfloat16* __restrict__ C2h, __nv_bfloat16* __restrict__ C2l) {
    extern __shared__ __align__(128) char smem[];
    const uint32_t sb = smem_u32(smem);
    const int t = threadIdx.x, lane = t & 31, w = t >> 5;
    const int wm = (w & 3) * 32, wn = (w >> 2) * 64;
    const int my = blockIdx.y, n0 = blockIdx.x << 7;
    const int z = HEADOUT ? blockIdx.z : 0;

    const __nv_bfloat16 *Aph, *Apl;
    int bsel = 0, tile = 0;
    if (HEADOUT && z > 0) {
        bsel = my >> 4; tile = my & 15;
        if ((tile << 7) >= g_cnt[bsel]) return;
        const size_t ao = ((size_t)(bsel * SEQ) + ((size_t)tile << 7)) * EMB;
        Aph = g_cxh + ao;  Apl = g_cxl + ao;
    } else {
        const size_t ao = ((size_t)my << 7) * EMB;
        Aph = Ah + ao;  Apl = Al + ao;
    }

    const __nv_bfloat16* Bh = WhBase + (size_t)z * EMB * EMB;
    const __nv_bfloat16* Bl = WlBase + (size_t)z * EMB * EMB;
    const float* bias = (z == 0) ? b0p : (z == 1 ? b1p : b2p);
    __nv_bfloat16* Ch = (z == 0) ? C0h : (z == 1 ? C1h : C2h);
    __nv_bfloat16* Cl = (z == 0) ? C0l : (z == 1 ? C1l : C2l);

    auto issue = [&](int kb, int st) {
        const uint32_t s0 = sb + st * 32768;
        const int kc = kb << 5;
#pragma unroll
        for (int i = 0; i < 2; i++) {
            int idx = t + (i << 8);
            int row = idx >> 2, ch = idx & 3;
            int so = SWZ32(row, ch);
            size_t ga = (size_t)row * EMB + kc + (ch << 3);
            size_t gb = (size_t)(n0 + row) * EMB + kc + (ch << 3);
            cp16(s0 +         so, Aph + ga);
            cp16(s0 +  8192 + so, Apl + ga);
            cp16(s0 + 16384 + so, Bh + gb);
            cp16(s0 + 24576 + so, Bl + gb);
        }
    };

    float c[2][8][4];
#pragma unroll
    for (int i = 0; i < 2; i++)
#pragma unroll
        for (int j = 0; j < 8; j++)
#pragma unroll
            for (int k = 0; k < 4; k++) c[i][j][k] = 0.f;

    issue(0, 0); CP_COMMIT();
    issue(1, 1); CP_COMMIT();

    for (int kb = 0; kb < 32; kb++) {
        CP_WAIT1();
        __syncthreads();
        if (kb + 2 < 32) issue(kb + 2, (kb + 2) % 3);
        CP_COMMIT();

        const uint32_t s0 = sb + (kb % 3) * 32768;
        const uint32_t sAh = s0, sAl = s0 + 8192, sBh = s0 + 16384, sBl = s0 + 24576;
#pragma unroll
        for (int s = 0; s < 2; s++) {
            const int ch = 2 * s + (lane >> 4);
            uint32_t ah[2][4], al[2][4];
#pragma unroll
            for (int mt = 0; mt < 2; mt++) {
                int r = wm + mt * 16 + (lane & 15);
                ldsm4(ah[mt], sAh + SWZ32(r, ch));
                ldsm4(al[mt], sAl + SWZ32(r, ch));
            }
            // g-pairs, term-major issue (reuse distance 8 per accumulator)
#pragma unroll
            for (int g2 = 0; g2 < 4; g2 += 2) {
                uint32_t bh[2][4], bl[2][4];
#pragma unroll
                for (int gg = 0; gg < 2; gg++) {
                    int r = wn + (g2 + gg) * 16 + (lane & 15);
                    ldsm4(bh[gg], sBh + SWZ32(r, ch));
                    ldsm4(bl[gg], sBl + SWZ32(r, ch));
                }
                // term 1: ah x bh
#pragma unroll
                for (int gg = 0; gg < 2; gg++)
#pragma unroll
                    for (int mt = 0; mt < 2; mt++) {
                        mma16816(c[mt][2*(g2+gg)],   ah[mt], bh[gg][0], bh[gg][2]);
                        mma16816(c[mt][2*(g2+gg)+1], ah[mt], bh[gg][1], bh[gg][3]);
                    }
                // term 2: ah x bl
#pragma unroll
                for (int gg = 0; gg < 2; gg++)
#pragma unroll
                    for (int mt = 0; mt < 2; mt++) {
                        mma16816(c[mt][2*(g2+gg)],   ah[mt], bl[gg][0], bl[gg][2]);
                        mma16816(c[mt][2*(g2+gg)+1], ah[mt], bl[gg][1], bl[gg][3]);
                    }
                // term 3: al x bh
#pragma unroll
                for (int gg = 0; gg < 2; gg++)
#pragma unroll
                    for (int mt = 0; mt < 2; mt++) {
                        mma16816(c[mt][2*(g2+gg)],   al[mt], bh[gg][0], bh[gg][2]);
                        mma16816(c[mt][2*(g2+gg)+1], al[mt], bh[gg][1], bh[gg][3]);
                    }
            }
        }
    }

#pragma unroll
    for (int mt = 0; mt < 2; mt++) {
#pragma unroll
        for (int nt = 0; nt < 8; nt++) {
            const int col = n0 + wn + nt * 8 + ((lane & 3) << 1);
            const float b0 = bias[col], b1 = bias[col + 1];
            const int r0 = wm + mt * 16 + (lane >> 2);
#pragma unroll
            for (int half = 0; half < 2; half++) {
                const int r = r0 + half * 8;
                const float v0 = c[mt][nt][half*2+0] + b0;
                const float v1 = c[mt][nt][half*2+1] + b1;
                if (HEADOUT) {
                    uint32_t h2, l2;
                    split2(v0, v1, h2, l2);
                    const int hd = col >> 6, d0 = col & 63;
                    size_t off;
                    if (z == 0) {
                        const int m = (my << 7) + r;
                        const int bb = m >> 11, srow = m & 2047;
                        off = (((size_t)(bb * NH + hd)) * SEQ + srow) * HD + d0;
                    } else {
                        const int j = (tile << 7) + r;
                        off = (((size_t)(bsel * NH + hd)) * SEQ + j) * HD + d0;
                    }
                    *(uint32_t*)(Ch + off) = h2;
                    *(uint32_t*)(Cl + off) = l2;
                } else {
                    const int m = (my << 7) + r;
                    *(float2*)(Co + (size_t)m * EMB + col) = make_float2(v0, v1);
                }
            }
        }
    }
}

// ---------------------------------------------------------------------------
// Flash attention over COMPACTED K/V — exact R11 WIN version (no split-K).
// smem: Q 32KB | KV stage0 32KB | KV stage1 32KB = 96KB, occ 2.
// ---------------------------------------------------------------------------
__global__ __launch_bounds__(256, 2)
void attn_mma() {
    extern __shared__ __align__(128) char smem[];
    char* pQh = smem;
    char* pQl = smem + 16384;
    const uint32_t sQh = smem_u32(pQh), sQl = smem_u32(pQl);
    const uint32_t sKV = smem_u32(smem + 32768);

    const int t = threadIdx.x, lane = t & 31, w = t >> 5;
    const int qb = blockIdx.x, h = blockIdx.y, b = blockIdx.z;
    const size_t base = ((size_t)(b * NH + h)) * SEQ * HD;
    const int n = g_cnt[b];
    const int ntiles = (n + 63) >> 6;

    auto issue_kv = [&](int kb, int st) {
        const uint32_t s0 = sKV + st * 32768;
#pragma unroll
        for (int i = 0; i < 2; i++) {
            int idx = t + (i << 8);
            int row = idx >> 3, ch = idx & 7;
            int so = SWZ(row, ch);
            size_t ga = base + (size_t)(kb * 64 + row) * HD + (ch << 3);
            cp16(s0 +         so, g_cKh + ga);
            cp16(s0 +  8192 + so, g_cKl + ga);
            cp16(s0 + 16384 + so, g_cVh + ga);
            cp16(s0 + 24576 + so, g_cVl + ga);
        }
    };

#pragma unroll
    for (int i = 0; i < 4; i++) {
        int idx = t + (i << 8);
        int row = idx >> 3, ch = idx & 7;
        int so = SWZ(row, ch);
        size_t ga = base + (size_t)(qb * 128 + row) * HD + (ch << 3);
        cp16(sQh + so, g_Qh + ga);
        cp16(sQl + so, g_Ql + ga);
    }
    issue_kv(0, 0); CP_COMMIT();

    float o[8][4];
#pragma unroll
    for (int i = 0; i < 8; i++)
#pragma unroll
        for (int j = 0; j < 4; j++) o[i][j] = 0.f;
    float mrow[2] = {-INFINITY, -INFINITY};
    float lsum[2] = {0.f, 0.f};

    for (int kb = 0; kb < ntiles; kb++) {
        CP_WAIT0();
        __syncthreads();
        if (kb + 1 < ntiles) issue_kv(kb + 1, (kb + 1) & 1);
        CP_COMMIT();

        const uint32_t s0 = sKV + (kb & 1) * 32768;
        const uint32_t sKh = s0, sKl = s0 + 8192, sVh = s0 + 16384, sVl = s0 + 24576;

        float c[8][4];
#pragma unroll
        for (int i = 0; i < 8; i++)
#pragma unroll
            for (int j = 0; j < 4; j++) c[i][j] = 0.f;
#pragma unroll
        for (int s = 0; s < 4; s++) {
            const int ch = 2 * s + (lane >> 4);
            uint32_t ah[4], al[4];
            const int rq = w * 16 + (lane & 15);
            ldsm4(ah, sQh + SWZ(rq, ch));
            ldsm4(al, sQl + SWZ(rq, ch));
#pragma unroll
            for (int g = 0; g < 4; g++) {
                const int rk = g * 16 + (lane & 15);
                uint32_t bh[4], bl[4];
                ldsm4(bh, sKh + SWZ(rk, ch));
                ldsm4(bl, sKl + SWZ(rk, ch));
                mma16816(c[2*g],   ah, bh[0], bh[2]);
                mma16816(c[2*g+1], ah, bh[1], bh[3]);
                mma16816(c[2*g],   ah, bl[0], bl[2]);
                mma16816(c[2*g+1], ah, bl[1], bl[3]);
                mma16816(c[2*g],   al, bh[0], bh[2]);
                mma16816(c[2*g+1], al, bh[1], bh[3]);
            }
        }

        // scale + validity select (pad cols -> exactly -1e9 -> weight 0)
        const int cb = (lane & 3) << 1;
#pragma unroll
        for (int nt = 0; nt < 8; nt++) {
            const int col = kb * 64 + nt * 8 + cb;
            const bool v0 = col < n, v1 = col + 1 < n;
            c[nt][0] = v0 ? c[nt][0] * 0.125f : -1.0e9f;
            c[nt][1] = v1 ? c[nt][1] * 0.125f : -1.0e9f;
            c[nt][2] = v0 ? c[nt][2] * 0.125f : -1.0e9f;
            c[nt][3] = v1 ? c[nt][3] * 0.125f : -1.0e9f;
        }

        float mxA = -INFINITY, mxB = -INFINITY;
#pragma unroll
        for (int nt = 0; nt < 8; nt++) {
            mxA = fmaxf(mxA, fmaxf(c[nt][0], c[nt][1]));
            mxB = fmaxf(mxB, fmaxf(c[nt][2], c[nt][3]));
        }
#pragma unroll
        for (int off = 1; off < 4; off <<= 1) {
            mxA = fmaxf(mxA, __shfl_xor_sync(0xffffffffu, mxA, off));
            mxB = fmaxf(mxB, __shfl_xor_sync(0xffffffffu, mxB, off));
        }
        const float nmA = fmaxf(mrow[0], mxA), nmB = fmaxf(mrow[1], mxB);
        const float scA = __expf(mrow[0] - nmA), scB = __expf(mrow[1] - nmB);
        mrow[0] = nmA; mrow[1] = nmB;
        float sA = 0.f, sB = 0.f;
#pragma unroll
        for (int nt = 0; nt < 8; nt++) {
            c[nt][0] = __expf(c[nt][0] - nmA);
            c[nt][1] = __expf(c[nt][1] - nmA);
            c[nt][2] = __expf(c[nt][2] - nmB);
            c[nt][3] = __expf(c[nt][3] - nmB);
            sA += c[nt][0] + c[nt][1];
            sB += c[nt][2] + c[nt][3];
        }
#pragma unroll
        for (int off = 1; off < 4; off <<= 1) {
            sA += __shfl_xor_sync(0xffffffffu, sA, off);
            sB += __shfl_xor_sync(0xffffffffu, sB, off);
        }
        lsum[0] = lsum[0] * scA + sA;
        lsum[1] = lsum[1] * scB + sB;
#pragma unroll
        for (int nt = 0; nt < 8; nt++) {
            o[nt][0] *= scA; o[nt][1] *= scA;
            o[nt][2] *= scB; o[nt][3] *= scB;
        }

#pragma unroll
        for (int kt = 0; kt < 4; kt++) {
            uint32_t ph[4], pl[4];
            split2(c[2*kt][0],   c[2*kt][1],   ph[0], pl[0]);
            split2(c[2*kt][2],   c[2*kt][3],   ph[1], pl[1]);
            split2(c[2*kt+1][0], c[2*kt+1][1], ph[2], pl[2]);
            split2(c[2*kt+1][2], c[2*kt+1][3], ph[3], pl[3]);
            const int rv = kt * 16 + (lane & 15);
#pragma unroll
            for (int g = 0; g < 4; g++) {
                const int chv = 2 * g + (lane >> 4);
                uint32_t vh[4], vl[4];
                ldsm4t(vh, sVh + SWZ(rv, chv));
                ldsm4t(vl, sVl + SWZ(rv, chv));
                mma16816(o[2*g],   ph, vh[0], vh[1]);
                mma16816(o[2*g+1], ph, vh[2], vh[3]);
                mma16816(o[2*g],   ph, vl[0], vl[1]);
                mma16816(o[2*g+1], ph, vl[2], vl[3]);
                mma16816(o[2*g],   pl, vh[0], vh[1]);
                mma16816(o[2*g+1], pl, vh[2], vh[3]);
            }
        }
    }

    const float iA = 1.f / lsum[0], iB = 1.f / lsum[1];
    const int rA = qb * 128 + w * 16 + (lane >> 2);
    const int colb = (lane & 3) << 1;
#pragma unroll
    for (int nt = 0; nt < 8; nt++) {
        const int col = h * HD + nt * 8 + colb;
        uint32_t h2, l2;
        split2(o[nt][0] * iA, o[nt][1] * iA, h2, l2);
        size_t off = ((size_t)b * SEQ + rA) * EMB + col;
        *(uint32_t*)(g_xh + off) = h2;
        *(uint32_t*)(g_xl + off) = l2;
        split2(o[nt][2] * iB, o[nt][3] * iB, h2, l2);
        off = ((size_t)b * SEQ + rA + 8) * EMB + col;
        *(uint32_t*)(g_xh + off) = h2;
        *(uint32_t*)(g_xl + off) = l2;
    }
}

// ---------------------------------------------------------------------------
extern "C" void kernel_launch(void* const* d_in, const int* in_sizes, int n_in,
                              void* d_out, int out_size) {
    const float* x  = (const float*)d_in[0];
    const int*  mask = (const int*)d_in[1];
    const float* Wq = (const float*)d_in[2];
    const float* bq = (const float*)d_in[3];
    const float* Wk = (const float*)d_in[4];
    const float* bk = (const float*)d_in[5];
    const float* Wv = (const float*)d_in[6];
    const float* bv = (const float*)d_in[7];
    const float* Wo = (const float*)d_in[8];
    const float* bo = (const float*)d_in[9];

    __nv_bfloat16 *xh, *xl, *wh, *wl, *Qh, *Ql, *cKh, *cKl, *cVh, *cVl;
    cudaGetSymbolAddress((void**)&xh, g_xh);
    cudaGetSymbolAddress((void**)&xl, g_xl);
    cudaGetSymbolAddress((void**)&wh, g_wh);
    cudaGetSymbolAddress((void**)&wl, g_wl);
    cudaGetSymbolAddress((void**)&Qh, g_Qh);
    cudaGetSymbolAddress((void**)&Ql, g_Ql);
    cudaGetSymbolAddress((void**)&cKh, g_cKh);
    cudaGetSymbolAddress((void**)&cKl, g_cKl);
    cudaGetSymbolAddress((void**)&cVh, g_cVh);
    cudaGetSymbolAddress((void**)&cVl, g_cVl);
    const size_t WS = (size_t)EMB * EMB;

    const int GEMM_SMEM = 3 * 32768;           // 96KB -> occ 2
    const int ATTN_SMEM = 98304;               // 96KB -> occ 2
    cudaFuncSetAttribute(gemm_mma<1>, cudaFuncAttributeMaxDynamicSharedMemorySize, GEMM_SMEM);
    cudaFuncSetAttribute(gemm_mma<0>, cudaFuncAttributeMaxDynamicSharedMemorySize, GEMM_SMEM);
    cudaFuncSetAttribute(attn_mma,    cudaFuncAttributeMaxDynamicSharedMemorySize, ATTN_SMEM);

    // compaction first (mask only), then split (also scatters compacted rows)
    compact_kernel<<<BSZ, 256>>>(mask);
    split_kernel<<<(MTOT*EMB)/4/256, 256>>>(x, xh, xl);
    tsplit4_kernel<<<dim3(32,32,4), dim3(32,8)>>>(Wq, Wk, Wv, Wo, wh, wl);

    // fused QKV projection: z=0 Q (all rows), z=1 K / z=2 V (compacted rows)
    gemm_mma<1><<<dim3(EMB/128, MTOT/128, 3), 256, GEMM_SMEM>>>(
        xh, xl, wh, wl, bq, bk, bv, nullptr, Qh, Ql, cKh, cKl, cVh, cVl);

    // attention over compacted keys -> bf16 hi/lo into xh/xl
    attn_mma<<<dim3(SEQ/128, NH, BSZ), 256, ATTN_SMEM>>>();

    // O projection -> fp32 d_out
    gemm_mma<0><<<dim3(EMB/128, MTOT/128, 1), 256, GEMM_SMEM>>>(
        xh, xl, wh + 3*WS, wl + 3*WS, bo, bo, bo, (float*)d_out,
        nullptr, nullptr, nullptr, nullptr, nullptr, nullptr);
}

// round 16
// speedup vs baseline: 1.0805x; 1.0325x over previous
#include <cuda_runtime.h>
#include <cuda_bf16.h>
#include <math.h>
#include <stdint.h>

#define BSZ 4
#define SEQ 2048
#define EMB 1024
#define NH 16
#define HD 64
#define MTOT (BSZ*SEQ)   // 8192

// ---------------- scratch (__device__ globals; no allocs allowed) ----------
static __device__ __align__(256) __nv_bfloat16 g_xh[(size_t)MTOT*EMB];
static __device__ __align__(256) __nv_bfloat16 g_xl[(size_t)MTOT*EMB];
static __device__ __align__(256) __nv_bfloat16 g_wh[4][(size_t)EMB*EMB];
static __device__ __align__(256) __nv_bfloat16 g_wl[4][(size_t)EMB*EMB];
static __device__ __align__(256) __nv_bfloat16 g_Qh[(size_t)MTOT*EMB];
static __device__ __align__(256) __nv_bfloat16 g_Ql[(size_t)MTOT*EMB];
// compacted x rows (unmasked keys only) — K/V projection input
static __device__ __align__(256) __nv_bfloat16 g_cxh[(size_t)MTOT*EMB];
static __device__ __align__(256) __nv_bfloat16 g_cxl[(size_t)MTOT*EMB];
// mask-compacted K/V (written directly by the K/V projection GEMM; pad rows 0)
static __device__ __align__(256) __nv_bfloat16 g_cKh[(size_t)MTOT*EMB];
static __device__ __align__(256) __nv_bfloat16 g_cKl[(size_t)MTOT*EMB];
static __device__ __align__(256) __nv_bfloat16 g_cVh[(size_t)MTOT*EMB];
static __device__ __align__(256) __nv_bfloat16 g_cVl[(size_t)MTOT*EMB];
static __device__ int g_cnt[BSZ];
static __device__ int g_idx[BSZ*SEQ];
static __device__ int g_pos[BSZ*SEQ];   // src row -> compacted slot (or -1)

// ---------------- helpers --------------------------------------------------
__device__ __forceinline__ uint32_t smem_u32(const void* p) {
    uint32_t a;
    asm("{ .reg .u64 t; cvta.to.shared.u64 t, %1; cvt.u32.u64 %0, t; }"
        : "=r"(a) : "l"(p));
    return a;
}
__device__ __forceinline__ void cp16(uint32_t dst, const void* src) {
    asm volatile("cp.async.cg.shared.global [%0], [%1], 16;" :: "r"(dst), "l"(src));
}
#define CP_COMMIT() asm volatile("cp.async.commit_group;" ::: "memory")
#define CP_WAIT1()  asm volatile("cp.async.wait_group 1;" ::: "memory")
#define CP_WAIT0()  asm volatile("cp.async.wait_group 0;" ::: "memory")

__device__ __forceinline__ void ldsm4(uint32_t r[4], uint32_t a) {
    asm volatile("ldmatrix.sync.aligned.m8n8.x4.shared.b16 {%0,%1,%2,%3}, [%4];"
        : "=r"(r[0]), "=r"(r[1]), "=r"(r[2]), "=r"(r[3]) : "r"(a));
}
__device__ __forceinline__ void ldsm4t(uint32_t r[4], uint32_t a) {
    asm volatile("ldmatrix.sync.aligned.m8n8.x4.trans.shared.b16 {%0,%1,%2,%3}, [%4];"
        : "=r"(r[0]), "=r"(r[1]), "=r"(r[2]), "=r"(r[3]) : "r"(a));
}
__device__ __forceinline__ void mma16816(float c[4], const uint32_t a[4],
                                         uint32_t b0, uint32_t b1) {
    asm volatile("mma.sync.aligned.m16n8k16.row.col.f32.bf16.bf16.f32 "
        "{%0,%1,%2,%3}, {%4,%5,%6,%7}, {%8,%9}, {%0,%1,%2,%3};"
        : "+f"(c[0]), "+f"(c[1]), "+f"(c[2]), "+f"(c[3])
        : "r"(a[0]), "r"(a[1]), "r"(a[2]), "r"(a[3]), "r"(b0), "r"(b1));
}
__device__ __forceinline__ void split2(float v0, float v1, uint32_t& h, uint32_t& l) {
    __nv_bfloat162 hh = __floats2bfloat162_rn(v0, v1);
    float r0 = v0 - __bfloat162float(hh.x);
    float r1 = v1 - __bfloat162float(hh.y);
    __nv_bfloat162 ll = __floats2bfloat162_rn(r0, r1);
    h = *reinterpret_cast<uint32_t*>(&hh);
    l = *reinterpret_cast<uint32_t*>(&ll);
}
// [rows x 64] bf16 tile (128B rows), XOR swizzle: 8 chunks of 16B per row
#define SWZ(r, ch) (((r) << 7) | (((unsigned)((ch) ^ (r)) & 7u) << 4))
// [rows x 32] bf16 tile (64B rows): conflict-free for 8-row ldmatrix groups
#define SWZ32(r, ch) (((r) << 6) | (((unsigned)((ch) ^ (((r) >> 1) & 3)) & 3u) << 4))

// ---------------------------------------------------------------------------
// per-batch compaction: indices + inverse map + count. Runs BEFORE split.
// ---------------------------------------------------------------------------
__global__ __launch_bounds__(256)
void compact_kernel(const int* __restrict__ mask) {
    __shared__ int woff[8];
    const int b = blockIdx.x, t = threadIdx.x, lane = t & 31, w = t >> 5;
    const int* m = mask + b * SEQ;
    int v[8], cnt = 0;
#pragma unroll
    for (int i = 0; i < 8; i++) { v[i] = m[t * 8 + i]; cnt += (v[i] != 0); }
    int inc = cnt;
#pragma unroll
    for (int off = 1; off < 32; off <<= 1) {
        int nv = __shfl_up_sync(0xffffffffu, inc, off);
        if (lane >= off) inc += nv;
    }
    if (lane == 31) woff[w] = inc;
    __syncthreads();
    if (t == 0) {
        int run = 0;
#pragma unroll
        for (int j = 0; j < 8; j++) { int tmp = woff[j]; woff[j] = run; run += tmp; }
        g_cnt[b] = run;
    }
    __syncthreads();
    int off = woff[w] + inc - cnt;   // exclusive prefix for this thread
#pragma unroll
    for (int i = 0; i < 8; i++) {
        if (v[i]) { g_idx[b * SEQ + off] = t * 8 + i; g_pos[b * SEQ + t * 8 + i] = off; off++; }
        else        g_pos[b * SEQ + t * 8 + i] = -1;
    }
}

// ---------------------------------------------------------------------------
// fp32 -> bf16 hi/lo split; additionally scatters compacted rows for K/V proj
// ---------------------------------------------------------------------------
__global__ __launch_bounds__(256)
void split_kernel(const float* __restrict__ src,
                  __nv_bfloat16* __restrict__ hi, __nv_bfloat16* __restrict__ lo) {
    size_t i = (size_t)blockIdx.x * 256 + threadIdx.x;   // float4 index
    float4 v = ((const float4*)src)[i];
    uint32_t h0, l0, h1, l1;
    split2(v.x, v.y, h0, l0);
    split2(v.z, v.w, h1, l1);
    ((uint32_t*)hi)[2*i+0] = h0;  ((uint32_t*)hi)[2*i+1] = h1;
    ((uint32_t*)lo)[2*i+0] = l0;  ((uint32_t*)lo)[2*i+1] = l1;
    const int row = (int)(i >> 8);           // 256 float4 per 1024-wide row
    const int j = g_pos[row];
    if (j >= 0) {
        const int b = row >> 11;
        const size_t d = (((size_t)(b * SEQ) + j) << 10) + ((i & 255) << 2);
        *(uint32_t*)(g_cxh + d)     = h0;  *(uint32_t*)(g_cxh + d + 2) = h1;
        *(uint32_t*)(g_cxl + d)     = l0;  *(uint32_t*)(g_cxl + d + 2) = l1;
    }
}

__global__ __launch_bounds__(256)
void tsplit4_kernel(const float* __restrict__ W0, const float* __restrict__ W1,
                    const float* __restrict__ W2, const float* __restrict__ W3,
                    __nv_bfloat16* __restrict__ ThB, __nv_bfloat16* __restrict__ TlB) {
    __shared__ float sm[32][33];
    const int tx = threadIdx.x, ty = threadIdx.y;
    const int n0 = blockIdx.x * 32, k0 = blockIdx.y * 32;
    const int z = blockIdx.z;
    const float* W = (z == 0) ? W0 : (z == 1 ? W1 : (z == 2 ? W2 : W3));
    __nv_bfloat16* Th = ThB + (size_t)z * EMB * EMB;
    __nv_bfloat16* Tl = TlB + (size_t)z * EMB * EMB;
#pragma unroll
    for (int r = ty; r < 32; r += 8)
        sm[r][tx] = W[(size_t)(k0 + r) * EMB + n0 + tx];
    __syncthreads();
#pragma unroll
    for (int r = ty; r < 32; r += 8) {
        float v = sm[tx][r];
        __nv_bfloat16 h = __float2bfloat16_rn(v);
        __nv_bfloat16 l = __float2bfloat16_rn(v - __bfloat162float(h));
        Th[(size_t)(n0 + r) * EMB + k0 + tx] = h;
        Tl[(size_t)(n0 + r) * EMB + k0 + tx] = l;
    }
}

// ---------------------------------------------------------------------------
// bf16x3 warp-MMA GEMM. R16: CTA tile 128x64 (warp m32 x n32, accum 32 regs),
// K-chunk 32, 3 stages x 24KB = 72KB smem -> occupancy 3 (24 warps/SM).
// Same K-order and per-accumulator term order as R11 -> bit-identical results.
// HEADOUT=1: z=0 Q (all rows); z=1,2 K,V over compacted rows (early exit).
// Stage layout: Ah 0 | Al 8K | Bh 16K | Bl 20K.
// ---------------------------------------------------------------------------
template<int HEADOUT>
__global__ __launch_bounds__(256, 3)
void gemm_mma(const __nv_bfloat16* __restrict__ Ah, const __nv_bfloat16* __restrict__ Al,
              const __nv_bfloat16* __restrict__ WhBase, const __nv_bfloat16* __restrict__ WlBase,
              const float* __restrict__ b0p, const float* __restrict__ b1p,
              const float* __restrict__ b2p, float* __restrict__ Co,
              __nv_bfloat16* __restrict__ C0h, __nv_bfloat16* __restrict__ C0l,
              __nv_bfloat16* __restrict__ C1h, __nv_bfloat16* __restrict__ C1l,
              __nv_bfloat16* __restrict__ C2h, __nv_bfloat16* __restrict__ C2l) {
    extern __shared__ __align__(128) char smem[];
    const uint32_t sb = smem_u32(smem);
    const int t = threadIdx.x, lane = t & 31, w = t >> 5;
    const int wm = (w & 3) * 32, wn = (w >> 2) * 32;
    const int my = blockIdx.y, n0 = blockIdx.x << 6;
    const int z = HEADOUT ? blockIdx.z : 0;

    const __nv_bfloat16 *Aph, *Apl;
    int bsel = 0, tile = 0;
    if (HEADOUT && z > 0) {
        bsel = my >> 4; tile = my & 15;
        if ((tile << 7) >= g_cnt[bsel]) return;
        const size_t ao = ((size_t)(bsel * SEQ) + ((size_t)tile << 7)) * EMB;
        Aph = g_cxh + ao;  Apl = g_cxl + ao;
    } else {
        const size_t ao = ((size_t)my << 7) * EMB;
        Aph = Ah + ao;  Apl = Al + ao;
    }

    const __nv_bfloat16* Bh = WhBase + (size_t)z * EMB * EMB;
    const __nv_bfloat16* Bl = WlBase + (size_t)z * EMB * EMB;
    const float* bias = (z == 0) ? b0p : (z == 1 ? b1p : b2p);
    __nv_bfloat16* Ch = (z == 0) ? C0h : (z == 1 ? C1h : C2h);
    __nv_bfloat16* Cl = (z == 0) ? C0l : (z == 1 ? C1l : C2l);

    // issue one 32-wide K-chunk into stage st (6 cp16 per thread)
    auto issue = [&](int kb, int st) {
        const uint32_t s0 = sb + st * 24576;
        const int kc = kb << 5;
#pragma unroll
        for (int i = 0; i < 2; i++) {               // A: 512 chunks (hi+lo)
            int idx = t + (i << 8);
            int row = idx >> 2, ch = idx & 3;
            int so = SWZ32(row, ch);
            size_t ga = (size_t)row * EMB + kc + (ch << 3);
            cp16(s0 +        so, Aph + ga);
            cp16(s0 + 8192 + so, Apl + ga);
        }
        {                                           // B: 256 chunks (hi+lo)
            int row = t >> 2, ch = t & 3;           // rows 0..63
            int so = SWZ32(row, ch);
            size_t gb = (size_t)(n0 + row) * EMB + kc + (ch << 3);
            cp16(s0 + 16384 + so, Bh + gb);
            cp16(s0 + 20480 + so, Bl + gb);
        }
    };

    float c[2][4][4];
#pragma unroll
    for (int i = 0; i < 2; i++)
#pragma unroll
        for (int j = 0; j < 4; j++)
#pragma unroll
            for (int k = 0; k < 4; k++) c[i][j][k] = 0.f;

    issue(0, 0); CP_COMMIT();
    issue(1, 1); CP_COMMIT();

    for (int kb = 0; kb < 32; kb++) {
        CP_WAIT1();
        __syncthreads();
        if (kb + 2 < 32) issue(kb + 2, (kb + 2) % 3);
        CP_COMMIT();   // empty group near tail keeps wait_group accounting valid

        const uint32_t s0 = sb + (kb % 3) * 24576;
        const uint32_t sAh = s0, sAl = s0 + 8192, sBh = s0 + 16384, sBl = s0 + 20480;
#pragma unroll
        for (int s = 0; s < 2; s++) {
            const int ch = 2 * s + (lane >> 4);
            uint32_t ah[2][4], al[2][4];
#pragma unroll
            for (int mt = 0; mt < 2; mt++) {
                int r = wm + mt * 16 + (lane & 15);
                ldsm4(ah[mt], sAh + SWZ32(r, ch));
                ldsm4(al[mt], sAl + SWZ32(r, ch));
            }
#pragma unroll
            for (int g = 0; g < 2; g++) {
                int r = wn + g * 16 + (lane & 15);
                uint32_t bh[4], bl[4];
                ldsm4(bh, sBh + SWZ32(r, ch));
                ldsm4(bl, sBl + SWZ32(r, ch));
#pragma unroll
                for (int mt = 0; mt < 2; mt++) {
                    mma16816(c[mt][2*g],   ah[mt], bh[0], bh[2]);
                    mma16816(c[mt][2*g+1], ah[mt], bh[1], bh[3]);
                    mma16816(c[mt][2*g],   ah[mt], bl[0], bl[2]);
                    mma16816(c[mt][2*g+1], ah[mt], bl[1], bl[3]);
                    mma16816(c[mt][2*g],   al[mt], bh[0], bh[2]);
                    mma16816(c[mt][2*g+1], al[mt], bh[1], bh[3]);
                }
            }
        }
    }

#pragma unroll
    for (int mt = 0; mt < 2; mt++) {
#pragma unroll
        for (int nt = 0; nt < 4; nt++) {
            const int col = n0 + wn + nt * 8 + ((lane & 3) << 1);
            const float b0 = bias[col], b1 = bias[col + 1];
            const int r0 = wm + mt * 16 + (lane >> 2);
#pragma unroll
            for (int half = 0; half < 2; half++) {
                const int r = r0 + half * 8;
                const float v0 = c[mt][nt][half*2+0] + b0;
                const float v1 = c[mt][nt][half*2+1] + b1;
                if (HEADOUT) {
                    uint32_t h2, l2;
                    split2(v0, v1, h2, l2);
                    const int hd = col >> 6, d0 = col & 63;
                    size_t off;
                    if (z == 0) {
                        const int m = (my << 7) + r;
                        const int bb = m >> 11, srow = m & 2047;
                        off = (((size_t)(bb * NH + hd)) * SEQ + srow) * HD + d0;
                    } else {
                        const int j = (tile << 7) + r;
                        off = (((size_t)(bsel * NH + hd)) * SEQ + j) * HD + d0;
                    }
                    *(uint32_t*)(Ch + off) = h2;
                    *(uint32_t*)(Cl + off) = l2;
                } else {
                    const int m = (my << 7) + r;
                    *(float2*)(Co + (size_t)m * EMB + col) = make_float2(v0, v1);
                }
            }
        }
    }
}

// ---------------------------------------------------------------------------
// Flash attention over COMPACTED K/V — exact R11 WIN version.
// smem: Q 32KB | KV stage0 32KB | KV stage1 32KB = 96KB, occ 2.
// ---------------------------------------------------------------------------
__global__ __launch_bounds__(256, 2)
void attn_mma() {
    extern __shared__ __align__(128) char smem[];
    char* pQh = smem;
    char* pQl = smem + 16384;
    const uint32_t sQh = smem_u32(pQh), sQl = smem_u32(pQl);
    const uint32_t sKV = smem_u32(smem + 32768);

    const int t = threadIdx.x, lane = t & 31, w = t >> 5;
    const int qb = blockIdx.x, h = blockIdx.y, b = blockIdx.z;
    const size_t base = ((size_t)(b * NH + h)) * SEQ * HD;
    const int n = g_cnt[b];
    const int ntiles = (n + 63) >> 6;

    auto issue_kv = [&](int kb, int st) {
        const uint32_t s0 = sKV + st * 32768;
#pragma unroll
        for (int i = 0; i < 2; i++) {
            int idx = t + (i << 8);
            int row = idx >> 3, ch = idx & 7;
            int so = SWZ(row, ch);
            size_t ga = base + (size_t)(kb * 64 + row) * HD + (ch << 3);
            cp16(s0 +         so, g_cKh + ga);
            cp16(s0 +  8192 + so, g_cKl + ga);
            cp16(s0 + 16384 + so, g_cVh + ga);
            cp16(s0 + 24576 + so, g_cVl + ga);
        }
    };

#pragma unroll
    for (int i = 0; i < 4; i++) {
        int idx = t + (i << 8);
        int row = idx >> 3, ch = idx & 7;
        int so = SWZ(row, ch);
        size_t ga = base + (size_t)(qb * 128 + row) * HD + (ch << 3);
        cp16(sQh + so, g_Qh + ga);
        cp16(sQl + so, g_Ql + ga);
    }
    issue_kv(0, 0); CP_COMMIT();

    float o[8][4];
#pragma unroll
    for (int i = 0; i < 8; i++)
#pragma unroll
        for (int j = 0; j < 4; j++) o[i][j] = 0.f;
    float mrow[2] = {-INFINITY, -INFINITY};
    float lsum[2] = {0.f, 0.f};

    for (int kb = 0; kb < ntiles; kb++) {
        CP_WAIT0();
        __syncthreads();
        if (kb + 1 < ntiles) issue_kv(kb + 1, (kb + 1) & 1);
        CP_COMMIT();

        const uint32_t s0 = sKV + (kb & 1) * 32768;
        const uint32_t sKh = s0, sKl = s0 + 8192, sVh = s0 + 16384, sVl = s0 + 24576;

        float c[8][4];
#pragma unroll
        for (int i = 0; i < 8; i++)
#pragma unroll
            for (int j = 0; j < 4; j++) c[i][j] = 0.f;
#pragma unroll
        for (int s = 0; s < 4; s++) {
            const int ch = 2 * s + (lane >> 4);
            uint32_t ah[4], al[4];
            const int rq = w * 16 + (lane & 15);
            ldsm4(ah, sQh + SWZ(rq, ch));
            ldsm4(al, sQl + SWZ(rq, ch));
#pragma unroll
            for (int g = 0; g < 4; g++) {
                const int rk = g * 16 + (lane & 15);
                uint32_t bh[4], bl[4];
                ldsm4(bh, sKh + SWZ(rk, ch));
                ldsm4(bl, sKl + SWZ(rk, ch));
                mma16816(c[2*g],   ah, bh[0], bh[2]);
                mma16816(c[2*g+1], ah, bh[1], bh[3]);
                mma16816(c[2*g],   ah, bl[0], bl[2]);
                mma16816(c[2*g+1], ah, bl[1], bl[3]);
                mma16816(c[2*g],   al, bh[0], bh[2]);
                mma16816(c[2*g+1], al, bh[1], bh[3]);
            }
        }

        // scale + validity select (pad cols -> exactly -1e9 -> weight 0)
        const int cb = (lane & 3) << 1;
#pragma unroll
        for (int nt = 0; nt < 8; nt++) {
            const int col = kb * 64 + nt * 8 + cb;
            const bool v0 = col < n, v1 = col + 1 < n;
            c[nt][0] = v0 ? c[nt][0] * 0.125f : -1.0e9f;
            c[nt][1] = v1 ? c[nt][1] * 0.125f : -1.0e9f;
            c[nt][2] = v0 ? c[nt][2] * 0.125f : -1.0e9f;
            c[nt][3] = v1 ? c[nt][3] * 0.125f : -1.0e9f;
        }

        float mxA = -INFINITY, mxB = -INFINITY;
#pragma unroll
        for (int nt = 0; nt < 8; nt++) {
            mxA = fmaxf(mxA, fmaxf(c[nt][0], c[nt][1]));
            mxB = fmaxf(mxB, fmaxf(c[nt][2], c[nt][3]));
        }
#pragma unroll
        for (int off = 1; off < 4; off <<= 1) {
            mxA = fmaxf(mxA, __shfl_xor_sync(0xffffffffu, mxA, off));
            mxB = fmaxf(mxB, __shfl_xor_sync(0xffffffffu, mxB, off));
        }
        const float nmA = fmaxf(mrow[0], mxA), nmB = fmaxf(mrow[1], mxB);
        const float scA = __expf(mrow[0] - nmA), scB = __expf(mrow[1] - nmB);
        mrow[0] = nmA; mrow[1] = nmB;
        float sA = 0.f, sB = 0.f;
#pragma unroll
        for (int nt = 0; nt < 8; nt++) {
            c[nt][0] = __expf(c[nt][0] - nmA);
            c[nt][1] = __expf(c[nt][1] - nmA);
            c[nt][2] = __expf(c[nt][2] - nmB);
            c[nt][3] = __expf(c[nt][3] - nmB);
            sA += c[nt][0] + c[nt][1];
            sB += c[nt][2] + c[nt][3];
        }
#pragma unroll
        for (int off = 1; off < 4; off <<= 1) {
            sA += __shfl_xor_sync(0xffffffffu, sA, off);
            sB += __shfl_xor_sync(0xffffffffu, sB, off);
        }
        lsum[0] = lsum[0] * scA + sA;
        lsum[1] = lsum[1] * scB + sB;
#pragma unroll
        for (int nt = 0; nt < 8; nt++) {
            o[nt][0] *= scA; o[nt][1] *= scA;
            o[nt][2] *= scB; o[nt][3] *= scB;
        }

#pragma unroll
        for (int kt = 0; kt < 4; kt++) {
            uint32_t ph[4], pl[4];
            split2(c[2*kt][0],   c[2*kt][1],   ph[0], pl[0]);
            split2(c[2*kt][2],   c[2*kt][3],   ph[1], pl[1]);
            split2(c[2*kt+1][0], c[2*kt+1][1], ph[2], pl[2]);
            split2(c[2*kt+1][2], c[2*kt+1][3], ph[3], pl[3]);
            const int rv = kt * 16 + (lane & 15);
#pragma unroll
            for (int g = 0; g < 4; g++) {
                const int chv = 2 * g + (lane >> 4);
                uint32_t vh[4], vl[4];
                ldsm4t(vh, sVh + SWZ(rv, chv));
                ldsm4t(vl, sVl + SWZ(rv, chv));
                mma16816(o[2*g],   ph, vh[0], vh[1]);
                mma16816(o[2*g+1], ph, vh[2], vh[3]);
                mma16816(o[2*g],   ph, vl[0], vl[1]);
                mma16816(o[2*g+1], ph, vl[2], vl[3]);
                mma16816(o[2*g],   pl, vh[0], vh[1]);
                mma16816(o[2*g+1], pl, vh[2], vh[3]);
            }
        }
    }

    const float iA = 1.f / lsum[0], iB = 1.f / lsum[1];
    const int rA = qb * 128 + w * 16 + (lane >> 2);
    const int colb = (lane & 3) << 1;
#pragma unroll
    for (int nt = 0; nt < 8; nt++) {
        const int col = h * HD + nt * 8 + colb;
        uint32_t h2, l2;
        split2(o[nt][0] * iA, o[nt][1] * iA, h2, l2);
        size_t off = ((size_t)b * SEQ + rA) * EMB + col;
        *(uint32_t*)(g_xh + off) = h2;
        *(uint32_t*)(g_xl + off) = l2;
        split2(o[nt][2] * iB, o[nt][3] * iB, h2, l2);
        off = ((size_t)b * SEQ + rA + 8) * EMB + col;
        *(uint32_t*)(g_xh + off) = h2;
        *(uint32_t*)(g_xl + off) = l2;
    }
}

// ---------------------------------------------------------------------------
extern "C" void kernel_launch(void* const* d_in, const int* in_sizes, int n_in,
                              void* d_out, int out_size) {
    const float* x  = (const float*)d_in[0];
    const int*  mask = (const int*)d_in[1];
    const float* Wq = (const float*)d_in[2];
    const float* bq = (const float*)d_in[3];
    const float* Wk = (const float*)d_in[4];
    const float* bk = (const float*)d_in[5];
    const float* Wv = (const float*)d_in[6];
    const float* bv = (const float*)d_in[7];
    const float* Wo = (const float*)d_in[8];
    const float* bo = (const float*)d_in[9];

    __nv_bfloat16 *xh, *xl, *wh, *wl, *Qh, *Ql, *cKh, *cKl, *cVh, *cVl;
    cudaGetSymbolAddress((void**)&xh, g_xh);
    cudaGetSymbolAddress((void**)&xl, g_xl);
    cudaGetSymbolAddress((void**)&wh, g_wh);
    cudaGetSymbolAddress((void**)&wl, g_wl);
    cudaGetSymbolAddress((void**)&Qh, g_Qh);
    cudaGetSymbolAddress((void**)&Ql, g_Ql);
    cudaGetSymbolAddress((void**)&cKh, g_cKh);
    cudaGetSymbolAddress((void**)&cKl, g_cKl);
    cudaGetSymbolAddress((void**)&cVh, g_cVh);
    cudaGetSymbolAddress((void**)&cVl, g_cVl);
    const size_t WS = (size_t)EMB * EMB;

    const int GEMM_SMEM = 3 * 24576;           // 72KB -> occ 3
    const int ATTN_SMEM = 98304;               // 96KB -> occ 2
    cudaFuncSetAttribute(gemm_mma<1>, cudaFuncAttributeMaxDynamicSharedMemorySize, GEMM_SMEM);
    cudaFuncSetAttribute(gemm_mma<0>, cudaFuncAttributeMaxDynamicSharedMemorySize, GEMM_SMEM);
    cudaFuncSetAttribute(attn_mma,    cudaFuncAttributeMaxDynamicSharedMemorySize, ATTN_SMEM);

    // compaction first (mask only), then split (also scatters compacted rows)
    compact_kernel<<<BSZ, 256>>>(mask);
    split_kernel<<<(MTOT*EMB)/4/256, 256>>>(x, xh, xl);
    tsplit4_kernel<<<dim3(32,32,4), dim3(32,8)>>>(Wq, Wk, Wv, Wo, wh, wl);

    // fused QKV projection: z=0 Q (all rows), z=1 K / z=2 V (compacted rows)
    gemm_mma<1><<<dim3(EMB/64, MTOT/128, 3), 256, GEMM_SMEM>>>(
        xh, xl, wh, wl, bq, bk, bv, nullptr, Qh, Ql, cKh, cKl, cVh, cVl);

    // attention over compacted keys -> bf16 hi/lo into xh/xl
    attn_mma<<<dim3(SEQ/128, NH, BSZ), 256, ATTN_SMEM>>>();

    // O projection -> fp32 d_out
    gemm_mma<0><<<dim3(EMB/64, MTOT/128, 1), 256, GEMM_SMEM>>>(
        xh, xl, wh + 3*WS, wl + 3*WS, bo, bo, bo, (float*)d_out,
        nullptr, nullptr, nullptr, nullptr, nullptr, nullptr);
}

// round 17
// speedup vs baseline: 1.0826x; 1.0019x over previous
#include <cuda_runtime.h>
#include <cuda_bf16.h>
#include <math.h>
#include <stdint.h>

#define BSZ 4
#define SEQ 2048
#define EMB 1024
#define NH 16
#define HD 64
#define MTOT (BSZ*SEQ)   // 8192

// ---------------- scratch (__device__ globals; no allocs allowed) ----------
static __device__ __align__(256) __nv_bfloat16 g_xh[(size_t)MTOT*EMB];
static __device__ __align__(256) __nv_bfloat16 g_xl[(size_t)MTOT*EMB];
static __device__ __align__(256) __nv_bfloat16 g_wh[4][(size_t)EMB*EMB];
static __device__ __align__(256) __nv_bfloat16 g_wl[4][(size_t)EMB*EMB];
static __device__ __align__(256) __nv_bfloat16 g_Qh[(size_t)MTOT*EMB];
static __device__ __align__(256) __nv_bfloat16 g_Ql[(size_t)MTOT*EMB];
// compacted x rows (unmasked keys only) — K/V projection input
static __device__ __align__(256) __nv_bfloat16 g_cxh[(size_t)MTOT*EMB];
static __device__ __align__(256) __nv_bfloat16 g_cxl[(size_t)MTOT*EMB];
// mask-compacted K/V (written directly by the K/V projection GEMM; pad rows 0)
static __device__ __align__(256) __nv_bfloat16 g_cKh[(size_t)MTOT*EMB];
static __device__ __align__(256) __nv_bfloat16 g_cKl[(size_t)MTOT*EMB];
static __device__ __align__(256) __nv_bfloat16 g_cVh[(size_t)MTOT*EMB];
static __device__ __align__(256) __nv_bfloat16 g_cVl[(size_t)MTOT*EMB];
static __device__ int g_cnt[BSZ];
static __device__ int g_idx[BSZ*SEQ];
static __device__ int g_pos[BSZ*SEQ];   // src row -> compacted slot (or -1)

// ---------------- helpers --------------------------------------------------
__device__ __forceinline__ uint32_t smem_u32(const void* p) {
    uint32_t a;
    asm("{ .reg .u64 t; cvta.to.shared.u64 t, %1; cvt.u32.u64 %0, t; }"
        : "=r"(a) : "l"(p));
    return a;
}
__device__ __forceinline__ void cp16(uint32_t dst, const void* src) {
    asm volatile("cp.async.cg.shared.global [%0], [%1], 16;" :: "r"(dst), "l"(src));
}
#define CP_COMMIT() asm volatile("cp.async.commit_group;" ::: "memory")
#define CP_WAIT1()  asm volatile("cp.async.wait_group 1;" ::: "memory")
#define CP_WAIT0()  asm volatile("cp.async.wait_group 0;" ::: "memory")

__device__ __forceinline__ void ldsm4(uint32_t r[4], uint32_t a) {
    asm volatile("ldmatrix.sync.aligned.m8n8.x4.shared.b16 {%0,%1,%2,%3}, [%4];"
        : "=r"(r[0]), "=r"(r[1]), "=r"(r[2]), "=r"(r[3]) : "r"(a));
}
__device__ __forceinline__ void ldsm4t(uint32_t r[4], uint32_t a) {
    asm volatile("ldmatrix.sync.aligned.m8n8.x4.trans.shared.b16 {%0,%1,%2,%3}, [%4];"
        : "=r"(r[0]), "=r"(r[1]), "=r"(r[2]), "=r"(r[3]) : "r"(a));
}
__device__ __forceinline__ void mma16816(float c[4], const uint32_t a[4],
                                         uint32_t b0, uint32_t b1) {
    asm volatile("mma.sync.aligned.m16n8k16.row.col.f32.bf16.bf16.f32 "
        "{%0,%1,%2,%3}, {%4,%5,%6,%7}, {%8,%9}, {%0,%1,%2,%3};"
        : "+f"(c[0]), "+f"(c[1]), "+f"(c[2]), "+f"(c[3])
        : "r"(a[0]), "r"(a[1]), "r"(a[2]), "r"(a[3]), "r"(b0), "r"(b1));
}
__device__ __forceinline__ float ex2(float x) {
    float y;
    asm("ex2.approx.f32 %0, %1;" : "=f"(y) : "f"(x));
    return y;
}
__device__ __forceinline__ void split2(float v0, float v1, uint32_t& h, uint32_t& l) {
    __nv_bfloat162 hh = __floats2bfloat162_rn(v0, v1);
    float r0 = v0 - __bfloat162float(hh.x);
    float r1 = v1 - __bfloat162float(hh.y);
    __nv_bfloat162 ll = __floats2bfloat162_rn(r0, r1);
    h = *reinterpret_cast<uint32_t*>(&hh);
    l = *reinterpret_cast<uint32_t*>(&ll);
}
// [rows x 64] bf16 tile (128B rows), XOR swizzle: 8 chunks of 16B per row
#define SWZ(r, ch) (((r) << 7) | (((unsigned)((ch) ^ (r)) & 7u) << 4))
// [rows x 32] bf16 tile (64B rows): conflict-free for 8-row ldmatrix groups
#define SWZ32(r, ch) (((r) << 6) | (((unsigned)((ch) ^ (((r) >> 1) & 3)) & 3u) << 4))

// ---------------------------------------------------------------------------
// per-batch compaction: indices + inverse map + count. Runs BEFORE split.
// ---------------------------------------------------------------------------
__global__ __launch_bounds__(256)
void compact_kernel(const int* __restrict__ mask) {
    __shared__ int woff[8];
    const int b = blockIdx.x, t = threadIdx.x, lane = t & 31, w = t >> 5;
    const int* m = mask + b * SEQ;
    int v[8], cnt = 0;
#pragma unroll
    for (int i = 0; i < 8; i++) { v[i] = m[t * 8 + i]; cnt += (v[i] != 0); }
    int inc = cnt;
#pragma unroll
    for (int off = 1; off < 32; off <<= 1) {
        int nv = __shfl_up_sync(0xffffffffu, inc, off);
        if (lane >= off) inc += nv;
    }
    if (lane == 31) woff[w] = inc;
    __syncthreads();
    if (t == 0) {
        int run = 0;
#pragma unroll
        for (int j = 0; j < 8; j++) { int tmp = woff[j]; woff[j] = run; run += tmp; }
        g_cnt[b] = run;
    }
    __syncthreads();
    int off = woff[w] + inc - cnt;   // exclusive prefix for this thread
#pragma unroll
    for (int i = 0; i < 8; i++) {
        if (v[i]) { g_idx[b * SEQ + off] = t * 8 + i; g_pos[b * SEQ + t * 8 + i] = off; off++; }
        else        g_pos[b * SEQ + t * 8 + i] = -1;
    }
}

// ---------------------------------------------------------------------------
// fp32 -> bf16 hi/lo split; additionally scatters compacted rows for K/V proj
// ---------------------------------------------------------------------------
__global__ __launch_bounds__(256)
void split_kernel(const float* __restrict__ src,
                  __nv_bfloat16* __restrict__ hi, __nv_bfloat16* __restrict__ lo) {
    size_t i = (size_t)blockIdx.x * 256 + threadIdx.x;   // float4 index
    float4 v = ((const float4*)src)[i];
    uint32_t h0, l0, h1, l1;
    split2(v.x, v.y, h0, l0);
    split2(v.z, v.w, h1, l1);
    ((uint32_t*)hi)[2*i+0] = h0;  ((uint32_t*)hi)[2*i+1] = h1;
    ((uint32_t*)lo)[2*i+0] = l0;  ((uint32_t*)lo)[2*i+1] = l1;
    const int row = (int)(i >> 8);           // 256 float4 per 1024-wide row
    const int j = g_pos[row];
    if (j >= 0) {
        const int b = row >> 11;
        const size_t d = (((size_t)(b * SEQ) + j) << 10) + ((i & 255) << 2);
        *(uint32_t*)(g_cxh + d)     = h0;  *(uint32_t*)(g_cxh + d + 2) = h1;
        *(uint32_t*)(g_cxl + d)     = l0;  *(uint32_t*)(g_cxl + d + 2) = l1;
    }
}

__global__ __launch_bounds__(256)
void tsplit4_kernel(const float* __restrict__ W0, const float* __restrict__ W1,
                    const float* __restrict__ W2, const float* __restrict__ W3,
                    __nv_bfloat16* __restrict__ ThB, __nv_bfloat16* __restrict__ TlB) {
    __shared__ float sm[32][33];
    const int tx = threadIdx.x, ty = threadIdx.y;
    const int n0 = blockIdx.x * 32, k0 = blockIdx.y * 32;
    const int z = blockIdx.z;
    const float* W = (z == 0) ? W0 : (z == 1 ? W1 : (z == 2 ? W2 : W3));
    __nv_bfloat16* Th = ThB + (size_t)z * EMB * EMB;
    __nv_bfloat16* Tl = TlB + (size_t)z * EMB * EMB;
#pragma unroll
    for (int r = ty; r < 32; r += 8)
        sm[r][tx] = W[(size_t)(k0 + r) * EMB + n0 + tx];
    __syncthreads();
#pragma unroll
    for (int r = ty; r < 32; r += 8) {
        float v = sm[tx][r];
        __nv_bfloat16 h = __float2bfloat16_rn(v);
        __nv_bfloat16 l = __float2bfloat16_rn(v - __bfloat162float(h));
        Th[(size_t)(n0 + r) * EMB + k0 + tx] = h;
        Tl[(size_t)(n0 + r) * EMB + k0 + tx] = l;
    }
}

// ---------------------------------------------------------------------------
// bf16x3 warp-MMA GEMM (R16 WIN, unchanged). CTA tile 128x64, K-chunk 32,
// 3 stages x 24KB = 72KB -> occupancy 3. Stage: Ah 0 | Al 8K | Bh 16K | Bl 20K.
// ---------------------------------------------------------------------------
template<int HEADOUT>
__global__ __launch_bounds__(256, 3)
void gemm_mma(const __nv_bfloat16* __restrict__ Ah, const __nv_bfloat16* __restrict__ Al,
              const __nv_bfloat16* __restrict__ WhBase, const __nv_bfloat16* __restrict__ WlBase,
              const float* __restrict__ b0p, const float* __restrict__ b1p,
              const float* __restrict__ b2p, float* __restrict__ Co,
              __nv_bfloat16* __restrict__ C0h, __nv_bfloat16* __restrict__ C0l,
              __nv_bfloat16* __restrict__ C1h, __nv_bfloat16* __restrict__ C1l,
              __nv_bfloat16* __restrict__ C2h, __nv_bfloat16* __restrict__ C2l) {
    extern __shared__ __align__(128) char smem[];
    const uint32_t sb = smem_u32(smem);
    const int t = threadIdx.x, lane = t & 31, w = t >> 5;
    const int wm = (w & 3) * 32, wn = (w >> 2) * 32;
    const int my = blockIdx.y, n0 = blockIdx.x << 6;
    const int z = HEADOUT ? blockIdx.z : 0;

    const __nv_bfloat16 *Aph, *Apl;
    int bsel = 0, tile = 0;
    if (HEADOUT && z > 0) {
        bsel = my >> 4; tile = my & 15;
        if ((tile << 7) >= g_cnt[bsel]) return;
        const size_t ao = ((size_t)(bsel * SEQ) + ((size_t)tile << 7)) * EMB;
        Aph = g_cxh + ao;  Apl = g_cxl + ao;
    } else {
        const size_t ao = ((size_t)my << 7) * EMB;
        Aph = Ah + ao;  Apl = Al + ao;
    }

    const __nv_bfloat16* Bh = WhBase + (size_t)z * EMB * EMB;
    const __nv_bfloat16* Bl = WlBase + (size_t)z * EMB * EMB;
    const float* bias = (z == 0) ? b0p : (z == 1 ? b1p : b2p);
    __nv_bfloat16* Ch = (z == 0) ? C0h : (z == 1 ? C1h : C2h);
    __nv_bfloat16* Cl = (z == 0) ? C0l : (z == 1 ? C1l : C2l);

    auto issue = [&](int kb, int st) {
        const uint32_t s0 = sb + st * 24576;
        const int kc = kb << 5;
#pragma unroll
        for (int i = 0; i < 2; i++) {               // A: 512 chunks (hi+lo)
            int idx = t + (i << 8);
            int row = idx >> 2, ch = idx & 3;
            int so = SWZ32(row, ch);
            size_t ga = (size_t)row * EMB + kc + (ch << 3);
            cp16(s0 +        so, Aph + ga);
            cp16(s0 + 8192 + so, Apl + ga);
        }
        {                                           // B: 256 chunks (hi+lo)
            int row = t >> 2, ch = t & 3;
            int so = SWZ32(row, ch);
            size_t gb = (size_t)(n0 + row) * EMB + kc + (ch << 3);
            cp16(s0 + 16384 + so, Bh + gb);
            cp16(s0 + 20480 + so, Bl + gb);
        }
    };

    float c[2][4][4];
#pragma unroll
    for (int i = 0; i < 2; i++)
#pragma unroll
        for (int j = 0; j < 4; j++)
#pragma unroll
            for (int k = 0; k < 4; k++) c[i][j][k] = 0.f;

    issue(0, 0); CP_COMMIT();
    issue(1, 1); CP_COMMIT();

    for (int kb = 0; kb < 32; kb++) {
        CP_WAIT1();
        __syncthreads();
        if (kb + 2 < 32) issue(kb + 2, (kb + 2) % 3);
        CP_COMMIT();

        const uint32_t s0 = sb + (kb % 3) * 24576;
        const uint32_t sAh = s0, sAl = s0 + 8192, sBh = s0 + 16384, sBl = s0 + 20480;
#pragma unroll
        for (int s = 0; s < 2; s++) {
            const int ch = 2 * s + (lane >> 4);
            uint32_t ah[2][4], al[2][4];
#pragma unroll
            for (int mt = 0; mt < 2; mt++) {
                int r = wm + mt * 16 + (lane & 15);
                ldsm4(ah[mt], sAh + SWZ32(r, ch));
                ldsm4(al[mt], sAl + SWZ32(r, ch));
            }
#pragma unroll
            for (int g = 0; g < 2; g++) {
                int r = wn + g * 16 + (lane & 15);
                uint32_t bh[4], bl[4];
                ldsm4(bh, sBh + SWZ32(r, ch));
                ldsm4(bl, sBl + SWZ32(r, ch));
#pragma unroll
                for (int mt = 0; mt < 2; mt++) {
                    mma16816(c[mt][2*g],   ah[mt], bh[0], bh[2]);
                    mma16816(c[mt][2*g+1], ah[mt], bh[1], bh[3]);
                    mma16816(c[mt][2*g],   ah[mt], bl[0], bl[2]);
                    mma16816(c[mt][2*g+1], ah[mt], bl[1], bl[3]);
                    mma16816(c[mt][2*g],   al[mt], bh[0], bh[2]);
                    mma16816(c[mt][2*g+1], al[mt], bh[1], bh[3]);
                }
            }
        }
    }

#pragma unroll
    for (int mt = 0; mt < 2; mt++) {
#pragma unroll
        for (int nt = 0; nt < 4; nt++) {
            const int col = n0 + wn + nt * 8 + ((lane & 3) << 1);
            const float b0 = bias[col], b1 = bias[col + 1];
            const int r0 = wm + mt * 16 + (lane >> 2);
#pragma unroll
            for (int half = 0; half < 2; half++) {
                const int r = r0 + half * 8;
                const float v0 = c[mt][nt][half*2+0] + b0;
                const float v1 = c[mt][nt][half*2+1] + b1;
                if (HEADOUT) {
                    uint32_t h2, l2;
                    split2(v0, v1, h2, l2);
                    const int hd = col >> 6, d0 = col & 63;
                    size_t off;
                    if (z == 0) {
                        const int m = (my << 7) + r;
                        const int bb = m >> 11, srow = m & 2047;
                        off = (((size_t)(bb * NH + hd)) * SEQ + srow) * HD + d0;
                    } else {
                        const int j = (tile << 7) + r;
                        off = (((size_t)(bsel * NH + hd)) * SEQ + j) * HD + d0;
                    }
                    *(uint32_t*)(Ch + off) = h2;
                    *(uint32_t*)(Cl + off) = l2;
                } else {
                    const int m = (my << 7) + r;
                    *(float2*)(Co + (size_t)m * EMB + col) = make_float2(v0, v1);
                }
            }
        }
    }
}

// ---------------------------------------------------------------------------
// Flash attention over COMPACTED K/V. R17: (a) Q fragments hoisted out of the
// key-tile loop (loop-invariant; removes 8 of 72 ldsm.x4 per warp-tile),
// (b) exp2-domain softmax (scale*log2e folded; raw ex2.approx, same HW unit).
// smem: Q 32KB | KV stage0 32KB | KV stage1 32KB = 96KB, occ 2.
// ---------------------------------------------------------------------------
__global__ __launch_bounds__(256, 2)
void attn_mma() {
    extern __shared__ __align__(128) char smem[];
    const uint32_t sQh = smem_u32(smem);
    const uint32_t sQl = sQh + 16384;
    const uint32_t sKV = sQh + 32768;

    const int t = threadIdx.x, lane = t & 31, w = t >> 5;
    const int qb = blockIdx.x, h = blockIdx.y, b = blockIdx.z;
    const size_t base = ((size_t)(b * NH + h)) * SEQ * HD;
    const int n = g_cnt[b];
    const int ntiles = (n + 63) >> 6;
    const float SC2 = 0.125f * 1.4426950408889634f;   // (1/8)*log2(e)

    auto issue_kv = [&](int kb, int st) {
        const uint32_t s0 = sKV + st * 32768;
#pragma unroll
        for (int i = 0; i < 2; i++) {
            int idx = t + (i << 8);
            int row = idx >> 3, ch = idx & 7;
            int so = SWZ(row, ch);
            size_t ga = base + (size_t)(kb * 64 + row) * HD + (ch << 3);
            cp16(s0 +         so, g_cKh + ga);
            cp16(s0 +  8192 + so, g_cKl + ga);
            cp16(s0 + 16384 + so, g_cVh + ga);
            cp16(s0 + 24576 + so, g_cVl + ga);
        }
    };

    // prologue: Q tile (group 0), then KV chunk 0 (group 1)
#pragma unroll
    for (int i = 0; i < 4; i++) {
        int idx = t + (i << 8);
        int row = idx >> 3, ch = idx & 7;
        int so = SWZ(row, ch);
        size_t ga = base + (size_t)(qb * 128 + row) * HD + (ch << 3);
        cp16(sQh + so, g_Qh + ga);
        cp16(sQl + so, g_Ql + ga);
    }
    CP_COMMIT();
    issue_kv(0, 0); CP_COMMIT();

    // wait group 0 (Q) done; hoist Q fragments into registers (loop-invariant)
    CP_WAIT1();
    __syncthreads();
    uint32_t qh[4][4], ql[4][4];
#pragma unroll
    for (int s = 0; s < 4; s++) {
        const int ch = 2 * s + (lane >> 4);
        const int rq = w * 16 + (lane & 15);
        ldsm4(qh[s], sQh + SWZ(rq, ch));
        ldsm4(ql[s], sQl + SWZ(rq, ch));
    }

    float o[8][4];
#pragma unroll
    for (int i = 0; i < 8; i++)
#pragma unroll
        for (int j = 0; j < 4; j++) o[i][j] = 0.f;
    float mrow[2] = {-INFINITY, -INFINITY};
    float lsum[2] = {0.f, 0.f};

    for (int kb = 0; kb < ntiles; kb++) {
        CP_WAIT0();
        __syncthreads();
        if (kb + 1 < ntiles) issue_kv(kb + 1, (kb + 1) & 1);
        CP_COMMIT();

        const uint32_t s0 = sKV + (kb & 1) * 32768;
        const uint32_t sKh = s0, sKl = s0 + 8192, sVh = s0 + 16384, sVl = s0 + 24576;

        float c[8][4];
#pragma unroll
        for (int i = 0; i < 8; i++)
#pragma unroll
            for (int j = 0; j < 4; j++) c[i][j] = 0.f;
#pragma unroll
        for (int s = 0; s < 4; s++) {
            const int ch = 2 * s + (lane >> 4);
#pragma unroll
            for (int g = 0; g < 4; g++) {
                const int rk = g * 16 + (lane & 15);
                uint32_t bh[4], bl[4];
                ldsm4(bh, sKh + SWZ(rk, ch));
                ldsm4(bl, sKl + SWZ(rk, ch));
                mma16816(c[2*g],   qh[s], bh[0], bh[2]);
                mma16816(c[2*g+1], qh[s], bh[1], bh[3]);
                mma16816(c[2*g],   qh[s], bl[0], bl[2]);
                mma16816(c[2*g+1], qh[s], bl[1], bl[3]);
                mma16816(c[2*g],   ql[s], bh[0], bh[2]);
                mma16816(c[2*g+1], ql[s], bh[1], bh[3]);
            }
        }

        // scale into exp2 domain + validity select (pad cols -> weight 0)
        const int cb = (lane & 3) << 1;
#pragma unroll
        for (int nt = 0; nt < 8; nt++) {
            const int col = kb * 64 + nt * 8 + cb;
            const bool v0 = col < n, v1 = col + 1 < n;
            c[nt][0] = v0 ? c[nt][0] * SC2 : -1.0e9f;
            c[nt][1] = v1 ? c[nt][1] * SC2 : -1.0e9f;
            c[nt][2] = v0 ? c[nt][2] * SC2 : -1.0e9f;
            c[nt][3] = v1 ? c[nt][3] * SC2 : -1.0e9f;
        }

        float mxA = -INFINITY, mxB = -INFINITY;
#pragma unroll
        for (int nt = 0; nt < 8; nt++) {
            mxA = fmaxf(mxA, fmaxf(c[nt][0], c[nt][1]));
            mxB = fmaxf(mxB, fmaxf(c[nt][2], c[nt][3]));
        }
#pragma unroll
        for (int off = 1; off < 4; off <<= 1) {
            mxA = fmaxf(mxA, __shfl_xor_sync(0xffffffffu, mxA, off));
            mxB = fmaxf(mxB, __shfl_xor_sync(0xffffffffu, mxB, off));
        }
        const float nmA = fmaxf(mrow[0], mxA), nmB = fmaxf(mrow[1], mxB);
        const float scA = ex2(mrow[0] - nmA), scB = ex2(mrow[1] - nmB);
        mrow[0] = nmA; mrow[1] = nmB;
        float sA = 0.f, sB = 0.f;
#pragma unroll
        for (int nt = 0; nt < 8; nt++) {
            c[nt][0] = ex2(c[nt][0] - nmA);
            c[nt][1] = ex2(c[nt][1] - nmA);
            c[nt][2] = ex2(c[nt][2] - nmB);
            c[nt][3] = ex2(c[nt][3] - nmB);
            sA += c[nt][0] + c[nt][1];
            sB += c[nt][2] + c[nt][3];
        }
#pragma unroll
        for (int off = 1; off < 4; off <<= 1) {
            sA += __shfl_xor_sync(0xffffffffu, sA, off);
            sB += __shfl_xor_sync(0xffffffffu, sB, off);
        }
        lsum[0] = lsum[0] * scA + sA;
        lsum[1] = lsum[1] * scB + sB;
#pragma unroll
        for (int nt = 0; nt < 8; nt++) {
            o[nt][0] *= scA; o[nt][1] *= scA;
            o[nt][2] *= scB; o[nt][3] *= scB;
        }

#pragma unroll
        for (int kt = 0; kt < 4; kt++) {
            uint32_t ph[4], pl[4];
            split2(c[2*kt][0],   c[2*kt][1],   ph[0], pl[0]);
            split2(c[2*kt][2],   c[2*kt][3],   ph[1], pl[1]);
            split2(c[2*kt+1][0], c[2*kt+1][1], ph[2], pl[2]);
            split2(c[2*kt+1][2], c[2*kt+1][3], ph[3], pl[3]);
            const int rv = kt * 16 + (lane & 15);
#pragma unroll
            for (int g = 0; g < 4; g++) {
                const int chv = 2 * g + (lane >> 4);
                uint32_t vh[4], vl[4];
                ldsm4t(vh, sVh + SWZ(rv, chv));
                ldsm4t(vl, sVl + SWZ(rv, chv));
                mma16816(o[2*g],   ph, vh[0], vh[1]);
                mma16816(o[2*g+1], ph, vh[2], vh[3]);
                mma16816(o[2*g],   ph, vl[0], vl[1]);
                mma16816(o[2*g+1], ph, vl[2], vl[3]);
                mma16816(o[2*g],   pl, vh[0], vh[1]);
                mma16816(o[2*g+1], pl, vh[2], vh[3]);
            }
        }
    }

    const float iA = 1.f / lsum[0], iB = 1.f / lsum[1];
    const int rA = qb * 128 + w * 16 + (lane >> 2);
    const int colb = (lane & 3) << 1;
#pragma unroll
    for (int nt = 0; nt < 8; nt++) {
        const int col = h * HD + nt * 8 + colb;
        uint32_t h2, l2;
        split2(o[nt][0] * iA, o[nt][1] * iA, h2, l2);
        size_t off = ((size_t)b * SEQ + rA) * EMB + col;
        *(uint32_t*)(g_xh + off) = h2;
        *(uint32_t*)(g_xl + off) = l2;
        split2(o[nt][2] * iB, o[nt][3] * iB, h2, l2);
        off = ((size_t)b * SEQ + rA + 8) * EMB + col;
        *(uint32_t*)(g_xh + off) = h2;
        *(uint32_t*)(g_xl + off) = l2;
    }
}

// ---------------------------------------------------------------------------
extern "C" void kernel_launch(void* const* d_in, const int* in_sizes, int n_in,
                              void* d_out, int out_size) {
    const float* x  = (const float*)d_in[0];
    const int*  mask = (const int*)d_in[1];
    const float* Wq = (const float*)d_in[2];
    const float* bq = (const float*)d_in[3];
    const float* Wk = (const float*)d_in[4];
    const float* bk = (const float*)d_in[5];
    const float* Wv = (const float*)d_in[6];
    const float* bv = (const float*)d_in[7];
    const float* Wo = (const float*)d_in[8];
    const float* bo = (const float*)d_in[9];

    __nv_bfloat16 *xh, *xl, *wh, *wl, *Qh, *Ql, *cKh, *cKl, *cVh, *cVl;
    cudaGetSymbolAddress((void**)&xh, g_xh);
    cudaGetSymbolAddress((void**)&xl, g_xl);
    cudaGetSymbolAddress((void**)&wh, g_wh);
    cudaGetSymbolAddress((void**)&wl, g_wl);
    cudaGetSymbolAddress((void**)&Qh, g_Qh);
    cudaGetSymbolAddress((void**)&Ql, g_Ql);
    cudaGetSymbolAddress((void**)&cKh, g_cKh);
    cudaGetSymbolAddress((void**)&cKl, g_cKl);
    cudaGetSymbolAddress((void**)&cVh, g_cVh);
    cudaGetSymbolAddress((void**)&cVl, g_cVl);
    const size_t WS = (size_t)EMB * EMB;

    const int GEMM_SMEM = 3 * 24576;           // 72KB -> occ 3
    const int ATTN_SMEM = 98304;               // 96KB -> occ 2
    cudaFuncSetAttribute(gemm_mma<1>, cudaFuncAttributeMaxDynamicSharedMemorySize, GEMM_SMEM);
    cudaFuncSetAttribute(gemm_mma<0>, cudaFuncAttributeMaxDynamicSharedMemorySize, GEMM_SMEM);
    cudaFuncSetAttribute(attn_mma,    cudaFuncAttributeMaxDynamicSharedMemorySize, ATTN_SMEM);

    // compaction first (mask only), then split (also scatters compacted rows)
    compact_kernel<<<BSZ, 256>>>(mask);
    split_kernel<<<(MTOT*EMB)/4/256, 256>>>(x, xh, xl);
    tsplit4_kernel<<<dim3(32,32,4), dim3(32,8)>>>(Wq, Wk, Wv, Wo, wh, wl);

    // fused QKV projection: z=0 Q (all rows), z=1 K / z=2 V (compacted rows)
    gemm_mma<1><<<dim3(EMB/64, MTOT/128, 3), 256, GEMM_SMEM>>>(
        xh, xl, wh, wl, bq, bk, bv, nullptr, Qh, Ql, cKh, cKl, cVh, cVl);

    // attention over compacted keys -> bf16 hi/lo into xh/xl
    attn_mma<<<dim3(SEQ/128, NH, BSZ), 256, ATTN_SMEM>>>();

    // O projection -> fp32 d_out
    gemm_mma<0><<<dim3(EMB/64, MTOT/128, 1), 256, GEMM_SMEM>>>(
        xh, xl, wh + 3*WS, wl + 3*WS, bo, bo, bo, (float*)d_out,
        nullptr, nullptr, nullptr, nullptr, nullptr, nullptr);
}